// round 2
// baseline (speedup 1.0000x reference)
#include <cuda_runtime.h>
#include <cuda_bf16.h>
#include <math.h>

// Problem constants: B=4, S=1024, D=1024, H=16, DK=64
#define BB 4
#define SS 1024
#define HH 16
#define DK 64
#define NEGV -10000000000.0f

// Scratch: projected+scaled Q2[b, i, h*64+d] and K2[b, j, h*64+d], fp32.
// 4*1024*1024 floats = 16MB each. Static device arrays (no allocation).
__device__ float g_Q2[BB * SS * HH * DK];
__device__ float g_K2[BB * SS * HH * DK];

// ---------------------------------------------------------------------------
// Projection kernel: for each row (b,h,i) of 64 inputs, compute
//   out[d] = tanh( sum_e W[d][e]*x[e] + bias[d] ) * (Wc ? Wc[h] : 1)
// and write to out[((b*1024)+i)*1024 + h*64 + d].
// Grid: 1024 blocks of 256 threads, 64 rows per block (one (b,h) slab each).
// ---------------------------------------------------------------------------
__global__ void __launch_bounds__(256)
proj_kernel(const float* __restrict__ x,
            const float* __restrict__ W,
            const float* __restrict__ bias,
            const float* __restrict__ Wc,   // nullptr => scale 1
            float* __restrict__ out)
{
    __shared__ float Ws[64 * 65];  // Ws[e*65 + d] = W[d*64 + e] (padded)
    __shared__ float xs[4][64];

    const int t = threadIdx.x;
    // Load W transposed into smem (padded to avoid write conflicts)
    for (int i = t; i < 4096; i += 256) {
        int d = i >> 6, e = i & 63;
        Ws[e * 65 + d] = W[i];
    }
    const int d  = t & 63;
    const int tg = t >> 6;                  // 0..3 row-group
    const float bv = bias[d];

    const int rowBase = blockIdx.x * 64;    // global row = (b*H + h)*1024 + i
    const int h  = (rowBase >> 10) & (HH - 1);
    const int bb = rowBase >> 14;           // / (H*S)
    const float scale = Wc ? Wc[h] : 1.0f;
    __syncthreads();

    for (int it = 0; it < 16; ++it) {
        const int r = rowBase + it * 4 + tg;
        xs[tg][d] = x[(size_t)r * 64 + d];
        __syncthreads();
        float acc = bv;
        #pragma unroll
        for (int e = 0; e < 64; ++e)
            acc = fmaf(Ws[e * 65 + d], xs[tg][e], acc);
        const float val = tanhf(acc) * scale;
        const int i = r & 1023;
        out[(size_t)((bb << 10) + i) * 1024 + h * 64 + d] = val;
        __syncthreads();
    }
}

// ---------------------------------------------------------------------------
// Batched SGEMM: C[b] = A[b] * B[b]^T, M=N=K=1024, 4 batches.
// 128x128 tile, BK=16, 256 threads, 8x8 per-thread microtile,
// double-buffered smem with register prefetch.
// ---------------------------------------------------------------------------
__global__ void __launch_bounds__(256, 2)
gemm_nt_kernel(const float* __restrict__ A, const float* __restrict__ B,
               float* __restrict__ C)
{
    const int LD = 1024;
    const size_t boff = (size_t)blockIdx.z * 1024 * 1024;
    A += boff; B += boff; C += boff;

    __shared__ float As[2][16][128];
    __shared__ float Bs[2][16][128];

    const int t  = threadIdx.x;
    const int tx = t & 15;        // N-dim thread coord
    const int ty = t >> 4;        // M-dim thread coord
    const int m0 = blockIdx.y * 128;
    const int n0 = blockIdx.x * 128;

    const int lr = t >> 2;            // 0..63, tile row (and +64)
    const int lk = (t & 3) << 2;      // 0,4,8,12

    const float* aptr = A + (size_t)(m0 + lr) * LD + lk;
    const float* bptr = B + (size_t)(n0 + lr) * LD + lk;

    float4 pa0 = *(const float4*)(aptr);
    float4 pa1 = *(const float4*)(aptr + 64 * LD);
    float4 pb0 = *(const float4*)(bptr);
    float4 pb1 = *(const float4*)(bptr + 64 * LD);

    float acc[8][8];
    #pragma unroll
    for (int i = 0; i < 8; ++i)
        #pragma unroll
        for (int j = 0; j < 8; ++j) acc[i][j] = 0.0f;

    // stage 0 into smem buffer 0
    #pragma unroll
    for (int j = 0; j < 4; ++j) {
        As[0][lk + j][lr]      = ((const float*)&pa0)[j];
        As[0][lk + j][lr + 64] = ((const float*)&pa1)[j];
        Bs[0][lk + j][lr]      = ((const float*)&pb0)[j];
        Bs[0][lk + j][lr + 64] = ((const float*)&pb1)[j];
    }
    __syncthreads();

    int buf = 0;
    for (int kt = 0; kt < 64; ++kt) {
        if (kt < 63) {
            const float* ap = aptr + (kt + 1) * 16;
            pa0 = *(const float4*)(ap);
            pa1 = *(const float4*)(ap + 64 * LD);
            const float* bp = bptr + (kt + 1) * 16;
            pb0 = *(const float4*)(bp);
            pb1 = *(const float4*)(bp + 64 * LD);
        }
        #pragma unroll
        for (int k = 0; k < 16; ++k) {
            float ar[8], br[8];
            #pragma unroll
            for (int i = 0; i < 8; ++i) ar[i] = As[buf][k][ty * 8 + i];
            #pragma unroll
            for (int j = 0; j < 8; ++j) br[j] = Bs[buf][k][tx * 8 + j];
            #pragma unroll
            for (int i = 0; i < 8; ++i)
                #pragma unroll
                for (int j = 0; j < 8; ++j)
                    acc[i][j] = fmaf(ar[i], br[j], acc[i][j]);
        }
        if (kt < 63) {
            __syncthreads();   // everyone done reading buf (protects next overwrite)
            const int nb = buf ^ 1;
            #pragma unroll
            for (int j = 0; j < 4; ++j) {
                As[nb][lk + j][lr]      = ((const float*)&pa0)[j];
                As[nb][lk + j][lr + 64] = ((const float*)&pa1)[j];
                Bs[nb][lk + j][lr]      = ((const float*)&pb0)[j];
                Bs[nb][lk + j][lr + 64] = ((const float*)&pb1)[j];
            }
            __syncthreads();
            buf = nb;
        }
    }

    #pragma unroll
    for (int i = 0; i < 8; ++i) {
        float* cp = C + (size_t)(m0 + ty * 8 + i) * LD + n0 + tx * 8;
        float4 v0 = make_float4(acc[i][0], acc[i][1], acc[i][2], acc[i][3]);
        float4 v1 = make_float4(acc[i][4], acc[i][5], acc[i][6], acc[i][7]);
        *(float4*)(cp)     = v0;
        *(float4*)(cp + 4) = v1;
    }
}

// ---------------------------------------------------------------------------
// Masked softmax over rows of 1024, in-place on C (= d_out).
// One block of 256 threads per row, 4 elements per thread.
// ---------------------------------------------------------------------------
__global__ void __launch_bounds__(256)
softmax_kernel(float* __restrict__ C, const int* __restrict__ mask,
               const float* __restrict__ bcp)
{
    const size_t row = blockIdx.x;
    float* p = C + row * 1024;
    const int* mp = mask + row * 1024;
    const int t = threadIdx.x;
    const float bias = bcp[0];

    float4 v = ((const float4*)p)[t];
    int4  mk = ((const int4*)mp)[t];

    float x0 = mk.x ? v.x + bias : NEGV;
    float x1 = mk.y ? v.y + bias : NEGV;
    float x2 = mk.z ? v.z + bias : NEGV;
    float x3 = mk.w ? v.w + bias : NEGV;

    float mx = fmaxf(fmaxf(x0, x1), fmaxf(x2, x3));
    #pragma unroll
    for (int o = 16; o; o >>= 1)
        mx = fmaxf(mx, __shfl_xor_sync(0xffffffffu, mx, o));

    __shared__ float red_m[8];
    __shared__ float red_s[8];
    if ((t & 31) == 0) red_m[t >> 5] = mx;
    __syncthreads();
    mx = red_m[0];
    #pragma unroll
    for (int i = 1; i < 8; ++i) mx = fmaxf(mx, red_m[i]);

    float e0 = expf(x0 - mx);
    float e1 = expf(x1 - mx);
    float e2 = expf(x2 - mx);
    float e3 = expf(x3 - mx);
    float s = e0 + e1 + e2 + e3;
    #pragma unroll
    for (int o = 16; o; o >>= 1)
        s += __shfl_xor_sync(0xffffffffu, s, o);
    if ((t & 31) == 0) red_s[t >> 5] = s;
    __syncthreads();
    float tot = red_s[0];
    #pragma unroll
    for (int i = 1; i < 8; ++i) tot += red_s[i];

    const float inv = 1.0f / tot;
    v.x = e0 * inv; v.y = e1 * inv; v.z = e2 * inv; v.w = e3 * inv;
    ((float4*)p)[t] = v;
}

// ---------------------------------------------------------------------------
// Launch
// ---------------------------------------------------------------------------
extern "C" void kernel_launch(void* const* d_in, const int* in_sizes, int n_in,
                              void* d_out, int out_size)
{
    const float* query = (const float*)d_in[0];
    const float* key   = (const float*)d_in[1];
    const int*   mask  = (const int*)  d_in[2];
    const float* Wq    = (const float*)d_in[3];
    const float* bq    = (const float*)d_in[4];
    const float* Wk    = (const float*)d_in[5];
    const float* bk    = (const float*)d_in[6];
    const float* Wc    = (const float*)d_in[7];
    const float* bc    = (const float*)d_in[8];
    float* out = (float*)d_out;

    float *q2, *k2;
    cudaGetSymbolAddress((void**)&q2, g_Q2);
    cudaGetSymbolAddress((void**)&k2, g_K2);

    // Project + fold Wc[h] into Q2; plain projection for K2.
    proj_kernel<<<1024, 256>>>(query, Wq, bq, Wc, q2);
    proj_kernel<<<1024, 256>>>(key,   Wk, bk, nullptr, k2);

    // comb[b] = Q2[b] @ K2[b]^T  (written straight into d_out)
    gemm_nt_kernel<<<dim3(8, 8, 4), 256>>>(q2, k2, out);

    // mask + softmax, in-place
    softmax_kernel<<<BB * SS, 256>>>(out, mask, bc);
}

// round 4
// speedup vs baseline: 1.6175x; 1.6175x over previous
#include <cuda_runtime.h>
#include <cuda_bf16.h>
#include <math.h>
#include <stdint.h>

// Problem constants: B=4, S=1024, D=1024, H=16, DK=64
#define BB 4
#define SS 1024
#define HH 16
#define KC 3072          // 3 slabs of 1024: hi|hi|lo (Q), hi|lo|hi (K)
#define NEGV -10000000000.0f

// Scratch: split-bf16 concatenated operands. 4*1024*3072*2B = 24MB each.
__device__ __nv_bfloat16 g_Qc[(size_t)BB * SS * KC];
__device__ __nv_bfloat16 g_Kc[(size_t)BB * SS * KC];

// ---------------------------------------------------------------------------
// Projection: out row (b,i) gets, at column h*64+d:
//   v = tanh(W x + b) * scale;  hi = bf16(v); lo = bf16(v - hi)
//   out[base+0] = hi; out[base+hiDup] = hi; out[base+loOff] = lo
// ---------------------------------------------------------------------------
__global__ void __launch_bounds__(256)
proj_kernel(const float* __restrict__ x,
            const float* __restrict__ W,
            const float* __restrict__ bias,
            const float* __restrict__ Wc,   // nullptr => scale 1
            __nv_bfloat16* __restrict__ out,
            int hiDup, int loOff)
{
    __shared__ float Ws[64 * 65];  // Ws[e*65 + d] = W[d*64 + e]
    __shared__ float xs[4][64];

    const int t = threadIdx.x;
    for (int i = t; i < 4096; i += 256) {
        int d = i >> 6, e = i & 63;
        Ws[e * 65 + d] = W[i];
    }
    const int d  = t & 63;
    const int tg = t >> 6;
    const float bv = bias[d];

    const int rowBase = blockIdx.x * 64;    // global row = (b*H + h)*1024 + i
    const int h  = (rowBase >> 10) & (HH - 1);
    const int bb = rowBase >> 14;
    const float scale = Wc ? Wc[h] : 1.0f;
    __syncthreads();

    for (int it = 0; it < 16; ++it) {
        const int r = rowBase + it * 4 + tg;
        xs[tg][d] = x[(size_t)r * 64 + d];
        __syncthreads();
        float acc = bv;
        #pragma unroll
        for (int e = 0; e < 64; ++e)
            acc = fmaf(Ws[e * 65 + d], xs[tg][e], acc);
        const float val = tanhf(acc) * scale;
        __nv_bfloat16 hi = __float2bfloat16(val);
        __nv_bfloat16 lo = __float2bfloat16(val - __bfloat162float(hi));
        const int i = r & 1023;
        size_t base = (size_t)((bb << 10) + i) * KC + h * 64 + d;
        out[base]         = hi;
        out[base + hiDup] = hi;
        out[base + loOff] = lo;
        __syncthreads();
    }
}

// ---------------------------------------------------------------------------
// bf16 NT GEMM: C[b] = A[b] * B[b]^T, M=N=1024, K=3072, 4 batches.
// 128x128 tile, BK=32, 256 threads (2x4 warps, 64x32 warp tiles),
// mma.sync m16n8k16, 3-stage cp.async pipeline, ldmatrix fragment loads.
// ---------------------------------------------------------------------------
__global__ void __launch_bounds__(256, 2)
gemm_bf16_nt(const __nv_bfloat16* __restrict__ A,
             const __nv_bfloat16* __restrict__ B,
             float* __restrict__ C)
{
    constexpr int BM = 128, BN = 128, BK = 32, LDS = 40, NSTAGE = 3;
    constexpr int KTILES = KC / BK;              // 96
    extern __shared__ __nv_bfloat16 sh[];

    const int t    = threadIdx.x;
    const int lane = t & 31;
    const int warp = t >> 5;
    const int wm   = warp & 1;                   // 0..1
    const int wn   = warp >> 1;                  // 0..3
    const int mW   = wm * 64;
    const int nW   = wn * 32;
    const int quad = lane >> 3;
    const int l7   = lane & 7;

    const size_t boff = (size_t)blockIdx.z * SS * KC;
    A += boff + (size_t)blockIdx.y * BM * KC;
    B += boff + (size_t)blockIdx.x * BN * KC;
    C += (size_t)blockIdx.z * SS * SS;

    const uint32_t sbase = (uint32_t)__cvta_generic_to_shared(sh);
    const uint32_t stageBytes = (uint32_t)(BM + BN) * LDS * 2;
    const uint32_t bOffBytes  = (uint32_t)BM * LDS * 2;

    // staging: each thread copies 2x16B of A and 2x16B of B per stage
    const int rS = t >> 2;          // 0..63
    const int cS = (t & 3) * 8;     // k element offset: 0,8,16,24
    const __nv_bfloat16* gA0 = A + (size_t)rS * KC + cS;
    const __nv_bfloat16* gA1 = A + (size_t)(rS + 64) * KC + cS;
    const __nv_bfloat16* gB0 = B + (size_t)rS * KC + cS;
    const __nv_bfloat16* gB1 = B + (size_t)(rS + 64) * KC + cS;
    const uint32_t dA0 = (uint32_t)(rS * LDS + cS) * 2;
    const uint32_t dA1 = (uint32_t)((rS + 64) * LDS + cS) * 2;

    #define LOAD_STAGE(kt, s)                                                   \
    do {                                                                        \
        uint32_t sb = sbase + (uint32_t)(s) * stageBytes;                       \
        int ko = (kt) * BK;                                                     \
        asm volatile("cp.async.cg.shared.global [%0], [%1], 16;" ::             \
            "r"(sb + dA0), "l"(gA0 + ko));                                      \
        asm volatile("cp.async.cg.shared.global [%0], [%1], 16;" ::             \
            "r"(sb + dA1), "l"(gA1 + ko));                                      \
        asm volatile("cp.async.cg.shared.global [%0], [%1], 16;" ::             \
            "r"(sb + bOffBytes + dA0), "l"(gB0 + ko));                          \
        asm volatile("cp.async.cg.shared.global [%0], [%1], 16;" ::             \
            "r"(sb + bOffBytes + dA1), "l"(gB1 + ko));                          \
    } while (0)

    float acc[4][4][4];
    #pragma unroll
    for (int mi = 0; mi < 4; ++mi)
        #pragma unroll
        for (int ni = 0; ni < 4; ++ni)
            #pragma unroll
            for (int r = 0; r < 4; ++r) acc[mi][ni][r] = 0.0f;

    // ldmatrix lane-address components (element offsets within a stage)
    // A: quad0: rows 0-7 @k0 | quad1: rows 8-15 @k0 | quad2: rows 0-7 @k8 | quad3: rows 8-15 @k8
    const int aRow  = mW + ((quad & 1) << 3) + l7;
    const int aKoff = (quad >> 1) << 3;
    // B pair p: quad0: nt(2p) @k0 | quad1: nt(2p) @k8 | quad2: nt(2p+1) @k0 | quad3: nt(2p+1) @k8
    const int bRowQ = ((quad >> 1) << 3) + l7;   // + p*16 + nW
    const int bKoff = (quad & 1) << 3;

    LOAD_STAGE(0, 0);
    asm volatile("cp.async.commit_group;");
    LOAD_STAGE(1, 1);
    asm volatile("cp.async.commit_group;");
    asm volatile("cp.async.wait_group 1;");
    __syncthreads();

    for (int kt = 0; kt < KTILES; ++kt) {
        if (kt + 2 < KTILES) {
            LOAD_STAGE(kt + 2, (kt + 2) % NSTAGE);
        }
        asm volatile("cp.async.commit_group;");

        const uint32_t sA = sbase + (uint32_t)(kt % NSTAGE) * stageBytes;
        const uint32_t sB = sA + bOffBytes;

        #pragma unroll
        for (int ks = 0; ks < 2; ++ks) {
            uint32_t ar[4][4];
            #pragma unroll
            for (int mi = 0; mi < 4; ++mi) {
                uint32_t addr = sA +
                    (uint32_t)((aRow + mi * 16) * LDS + ks * 16 + aKoff) * 2;
                asm volatile(
                    "ldmatrix.sync.aligned.m8n8.x4.shared.b16 {%0,%1,%2,%3}, [%4];"
                    : "=r"(ar[mi][0]), "=r"(ar[mi][1]),
                      "=r"(ar[mi][2]), "=r"(ar[mi][3])
                    : "r"(addr));
            }
            uint32_t br[4][2];
            #pragma unroll
            for (int p = 0; p < 2; ++p) {
                uint32_t addr = sB +
                    (uint32_t)((nW + p * 16 + bRowQ) * LDS + ks * 16 + bKoff) * 2;
                uint32_t r0, r1, r2, r3;
                asm volatile(
                    "ldmatrix.sync.aligned.m8n8.x4.shared.b16 {%0,%1,%2,%3}, [%4];"
                    : "=r"(r0), "=r"(r1), "=r"(r2), "=r"(r3)
                    : "r"(addr));
                br[2 * p][0]     = r0; br[2 * p][1]     = r1;
                br[2 * p + 1][0] = r2; br[2 * p + 1][1] = r3;
            }
            #pragma unroll
            for (int mi = 0; mi < 4; ++mi)
                #pragma unroll
                for (int ni = 0; ni < 4; ++ni)
                    asm volatile(
                        "mma.sync.aligned.m16n8k16.row.col.f32.bf16.bf16.f32 "
                        "{%0,%1,%2,%3}, {%4,%5,%6,%7}, {%8,%9}, {%0,%1,%2,%3};"
                        : "+f"(acc[mi][ni][0]), "+f"(acc[mi][ni][1]),
                          "+f"(acc[mi][ni][2]), "+f"(acc[mi][ni][3])
                        : "r"(ar[mi][0]), "r"(ar[mi][1]),
                          "r"(ar[mi][2]), "r"(ar[mi][3]),
                          "r"(br[ni][0]), "r"(br[ni][1]));
        }

        asm volatile("cp.async.wait_group 1;");
        __syncthreads();
    }

    // epilogue: write fp32 C
    #pragma unroll
    for (int mi = 0; mi < 4; ++mi) {
        #pragma unroll
        for (int ni = 0; ni < 4; ++ni) {
            int row = blockIdx.y * BM + mW + mi * 16 + (lane >> 2);
            int col = blockIdx.x * BN + nW + ni * 8 + ((lane & 3) << 1);
            float2 v0 = make_float2(acc[mi][ni][0], acc[mi][ni][1]);
            float2 v1 = make_float2(acc[mi][ni][2], acc[mi][ni][3]);
            *(float2*)&C[(size_t)row * SS + col]       = v0;
            *(float2*)&C[(size_t)(row + 8) * SS + col] = v1;
        }
    }
    #undef LOAD_STAGE
}

// ---------------------------------------------------------------------------
// Masked softmax over rows of 1024, in-place on C (= d_out).
// ---------------------------------------------------------------------------
__global__ void __launch_bounds__(256)
softmax_kernel(float* __restrict__ C, const int* __restrict__ mask,
               const float* __restrict__ bcp)
{
    const size_t row = blockIdx.x;
    float* p = C + row * 1024;
    const int* mp = mask + row * 1024;
    const int t = threadIdx.x;
    const float bias = bcp[0];

    float4 v = ((const float4*)p)[t];
    int4  mk = ((const int4*)mp)[t];

    float x0 = mk.x ? v.x + bias : NEGV;
    float x1 = mk.y ? v.y + bias : NEGV;
    float x2 = mk.z ? v.z + bias : NEGV;
    float x3 = mk.w ? v.w + bias : NEGV;

    float mx = fmaxf(fmaxf(x0, x1), fmaxf(x2, x3));
    #pragma unroll
    for (int o = 16; o; o >>= 1)
        mx = fmaxf(mx, __shfl_xor_sync(0xffffffffu, mx, o));

    __shared__ float red_m[8];
    __shared__ float red_s[8];
    if ((t & 31) == 0) red_m[t >> 5] = mx;
    __syncthreads();
    mx = red_m[0];
    #pragma unroll
    for (int i = 1; i < 8; ++i) mx = fmaxf(mx, red_m[i]);

    float e0 = expf(x0 - mx);
    float e1 = expf(x1 - mx);
    float e2 = expf(x2 - mx);
    float e3 = expf(x3 - mx);
    float s = e0 + e1 + e2 + e3;
    #pragma unroll
    for (int o = 16; o; o >>= 1)
        s += __shfl_xor_sync(0xffffffffu, s, o);
    if ((t & 31) == 0) red_s[t >> 5] = s;
    __syncthreads();
    float tot = red_s[0];
    #pragma unroll
    for (int i = 1; i < 8; ++i) tot += red_s[i];

    const float inv = 1.0f / tot;
    v.x = e0 * inv; v.y = e1 * inv; v.z = e2 * inv; v.w = e3 * inv;
    ((float4*)p)[t] = v;
}

// ---------------------------------------------------------------------------
// Launch
// ---------------------------------------------------------------------------
extern "C" void kernel_launch(void* const* d_in, const int* in_sizes, int n_in,
                              void* d_out, int out_size)
{
    const float* query = (const float*)d_in[0];
    const float* key   = (const float*)d_in[1];
    const int*   mask  = (const int*)  d_in[2];
    const float* Wq    = (const float*)d_in[3];
    const float* bq    = (const float*)d_in[4];
    const float* Wk    = (const float*)d_in[5];
    const float* bk    = (const float*)d_in[6];
    const float* Wc    = (const float*)d_in[7];
    const float* bc    = (const float*)d_in[8];
    float* out = (float*)d_out;

    __nv_bfloat16 *qc, *kc;
    cudaGetSymbolAddress((void**)&qc, g_Qc);
    cudaGetSymbolAddress((void**)&kc, g_Kc);

    const int smemBytes = 3 * (128 + 128) * 40 * 2;   // 61440
    cudaFuncSetAttribute(gemm_bf16_nt,
                         cudaFuncAttributeMaxDynamicSharedMemorySize, smemBytes);

    // Q slabs: [hi | hi | lo]; K slabs: [hi | lo | hi]
    proj_kernel<<<1024, 256>>>(query, Wq, bq, Wc, qc, 1024, 2048);
    proj_kernel<<<1024, 256>>>(key,   Wk, bk, nullptr, kc, 2048, 1024);

    // comb[b] = Qc[b] @ Kc[b]^T  (K=3072 encodes hi*hi + hi*lo + lo*hi)
    gemm_bf16_nt<<<dim3(8, 8, 4), 256, smemBytes>>>(qc, kc, out);

    // mask + softmax, in-place
    softmax_kernel<<<BB * SS, 256>>>(out, mask, bc);
}

// round 7
// speedup vs baseline: 1.9938x; 1.2327x over previous
#include <cuda_runtime.h>
#include <cuda_fp16.h>
#include <math.h>
#include <stdint.h>

// Problem constants: B=4, S=1024, D=1024, H=16, DK=64
#define BB 4
#define SS 1024
#define HH 16
#define KC 2048          // 2 slabs of 1024: Q=[hi|lo], K=[hi|hi]  (fp16 split)
#define NEGV -10000000000.0f

// Scratch: split-fp16 concatenated operands. 4*1024*2048*2B = 16MB each.
__device__ __half g_Qc[(size_t)BB * SS * KC];
__device__ __half g_Kc[(size_t)BB * SS * KC];

// ---------------------------------------------------------------------------
// Merged projection kernel: blocks 0..1023 -> Q path, 1024..2047 -> K path.
// out row (b,i), col h*64+d: v = tanh(Wx+b)*scale, split to fp16 hi/lo.
// Q writes [hi | lo]; K writes [hi | hi].
// ---------------------------------------------------------------------------
__global__ void __launch_bounds__(256)
proj2_kernel(const float* __restrict__ qin, const float* __restrict__ kin,
             const float* __restrict__ Wq, const float* __restrict__ bq,
             const float* __restrict__ Wk, const float* __restrict__ bk,
             const float* __restrict__ Wc,
             __half* __restrict__ qc, __half* __restrict__ kc)
{
    const bool isQ = blockIdx.x < 1024;
    const float* x    = isQ ? qin : kin;
    const float* W    = isQ ? Wq : Wk;
    const float* bias = isQ ? bq : bk;
    __half* out = isQ ? qc : kc;
    const int blk = blockIdx.x & 1023;

    __shared__ float Ws[64 * 65];   // Ws[e*65 + d] = W[d*64 + e]
    __shared__ float xs[4][64];

    const int t = threadIdx.x;
    for (int i = t; i < 4096; i += 256) {
        int d = i >> 6, e = i & 63;
        Ws[e * 65 + d] = W[i];
    }
    const int d  = t & 63;
    const int tg = t >> 6;
    const float bv = bias[d];

    const int rowBase = blk * 64;           // global row = (b*H + h)*1024 + i
    const int h  = (rowBase >> 10) & (HH - 1);
    const int bb = rowBase >> 14;
    const float scale = isQ ? Wc[h] : 1.0f;
    __syncthreads();

    for (int it = 0; it < 16; ++it) {
        const int r = rowBase + it * 4 + tg;
        xs[tg][d] = x[(size_t)r * 64 + d];
        __syncthreads();
        float acc = bv;
        #pragma unroll
        for (int e = 0; e < 64; ++e)
            acc = fmaf(Ws[e * 65 + d], xs[tg][e], acc);
        const float val = tanhf(acc) * scale;
        const __half hi = __float2half(val);
        const __half sec = isQ ? __float2half(val - __half2float(hi)) : hi;
        const int i = r & 1023;
        size_t base = (size_t)((bb << 10) + i) * KC + h * 64 + d;
        out[base]        = hi;
        out[base + 1024] = sec;
        __syncthreads();
    }
}

// ---------------------------------------------------------------------------
// fp16 NT GEMM: C[b] = A[b] * B[b]^T, M=N=1024, K=2048, 4 batches.
// 128x128 tile, BK=32, 256 threads (2x4 warps, 64x32 warp tiles),
// mma.sync m16n8k16.f16, 3-stage cp.async pipeline, ldmatrix loads.
// ---------------------------------------------------------------------------
__global__ void __launch_bounds__(256, 2)
gemm_fp16_nt(const __half* __restrict__ A,
             const __half* __restrict__ B,
             float* __restrict__ C)
{
    constexpr int BM = 128, BN = 128, BK = 32, LDS = 40, NSTAGE = 3;
    constexpr int KTILES = KC / BK;              // 64
    extern __shared__ __half sh[];

    const int t    = threadIdx.x;
    const int lane = t & 31;
    const int warp = t >> 5;
    const int wm   = warp & 1;
    const int wn   = warp >> 1;
    const int mW   = wm * 64;
    const int nW   = wn * 32;
    const int quad = lane >> 3;
    const int l7   = lane & 7;

    const size_t boff = (size_t)blockIdx.z * SS * KC;
    A += boff + (size_t)blockIdx.y * BM * KC;
    B += boff + (size_t)blockIdx.x * BN * KC;
    C += (size_t)blockIdx.z * SS * SS;

    const uint32_t sbase = (uint32_t)__cvta_generic_to_shared(sh);
    const uint32_t stageBytes = (uint32_t)(BM + BN) * LDS * 2;
    const uint32_t bOffBytes  = (uint32_t)BM * LDS * 2;

    // staging: each thread copies 2x16B of A and 2x16B of B per stage
    const int rS = t >> 2;          // 0..63
    const int cS = (t & 3) * 8;     // k offset: 0,8,16,24
    const __half* gA0 = A + (size_t)rS * KC + cS;
    const __half* gA1 = A + (size_t)(rS + 64) * KC + cS;
    const __half* gB0 = B + (size_t)rS * KC + cS;
    const __half* gB1 = B + (size_t)(rS + 64) * KC + cS;
    const uint32_t dA0 = (uint32_t)(rS * LDS + cS) * 2;
    const uint32_t dA1 = (uint32_t)((rS + 64) * LDS + cS) * 2;

    #define LOAD_STAGE(kt, s)                                                   \
    do {                                                                        \
        uint32_t sb = sbase + (uint32_t)(s) * stageBytes;                       \
        int ko = (kt) * BK;                                                     \
        asm volatile("cp.async.cg.shared.global [%0], [%1], 16;" ::             \
            "r"(sb + dA0), "l"(gA0 + ko));                                      \
        asm volatile("cp.async.cg.shared.global [%0], [%1], 16;" ::             \
            "r"(sb + dA1), "l"(gA1 + ko));                                      \
        asm volatile("cp.async.cg.shared.global [%0], [%1], 16;" ::             \
            "r"(sb + bOffBytes + dA0), "l"(gB0 + ko));                          \
        asm volatile("cp.async.cg.shared.global [%0], [%1], 16;" ::             \
            "r"(sb + bOffBytes + dA1), "l"(gB1 + ko));                          \
    } while (0)

    float acc[4][4][4];
    #pragma unroll
    for (int mi = 0; mi < 4; ++mi)
        #pragma unroll
        for (int ni = 0; ni < 4; ++ni)
            #pragma unroll
            for (int r = 0; r < 4; ++r) acc[mi][ni][r] = 0.0f;

    const int aRow  = mW + ((quad & 1) << 3) + l7;
    const int aKoff = (quad >> 1) << 3;
    const int bRowQ = ((quad >> 1) << 3) + l7;
    const int bKoff = (quad & 1) << 3;

    LOAD_STAGE(0, 0);
    asm volatile("cp.async.commit_group;");
    LOAD_STAGE(1, 1);
    asm volatile("cp.async.commit_group;");
    asm volatile("cp.async.wait_group 1;");
    __syncthreads();

    for (int kt = 0; kt < KTILES; ++kt) {
        if (kt + 2 < KTILES) {
            LOAD_STAGE(kt + 2, (kt + 2) % NSTAGE);
        }
        asm volatile("cp.async.commit_group;");

        const uint32_t sA = sbase + (uint32_t)(kt % NSTAGE) * stageBytes;
        const uint32_t sB = sA + bOffBytes;

        #pragma unroll
        for (int ks = 0; ks < 2; ++ks) {
            uint32_t ar[4][4];
            #pragma unroll
            for (int mi = 0; mi < 4; ++mi) {
                uint32_t addr = sA +
                    (uint32_t)((aRow + mi * 16) * LDS + ks * 16 + aKoff) * 2;
                asm volatile(
                    "ldmatrix.sync.aligned.m8n8.x4.shared.b16 {%0,%1,%2,%3}, [%4];"
                    : "=r"(ar[mi][0]), "=r"(ar[mi][1]),
                      "=r"(ar[mi][2]), "=r"(ar[mi][3])
                    : "r"(addr));
            }
            uint32_t br[4][2];
            #pragma unroll
            for (int p = 0; p < 2; ++p) {
                uint32_t addr = sB +
                    (uint32_t)((nW + p * 16 + bRowQ) * LDS + ks * 16 + bKoff) * 2;
                uint32_t r0, r1, r2, r3;
                asm volatile(
                    "ldmatrix.sync.aligned.m8n8.x4.shared.b16 {%0,%1,%2,%3}, [%4];"
                    : "=r"(r0), "=r"(r1), "=r"(r2), "=r"(r3)
                    : "r"(addr));
                br[2 * p][0]     = r0; br[2 * p][1]     = r1;
                br[2 * p + 1][0] = r2; br[2 * p + 1][1] = r3;
            }
            #pragma unroll
            for (int mi = 0; mi < 4; ++mi)
                #pragma unroll
                for (int ni = 0; ni < 4; ++ni)
                    asm volatile(
                        "mma.sync.aligned.m16n8k16.row.col.f32.f16.f16.f32 "
                        "{%0,%1,%2,%3}, {%4,%5,%6,%7}, {%8,%9}, {%0,%1,%2,%3};"
                        : "+f"(acc[mi][ni][0]), "+f"(acc[mi][ni][1]),
                          "+f"(acc[mi][ni][2]), "+f"(acc[mi][ni][3])
                        : "r"(ar[mi][0]), "r"(ar[mi][1]),
                          "r"(ar[mi][2]), "r"(ar[mi][3]),
                          "r"(br[ni][0]), "r"(br[ni][1]));
        }

        asm volatile("cp.async.wait_group 1;");
        __syncthreads();
    }

    // epilogue: write fp32 C
    #pragma unroll
    for (int mi = 0; mi < 4; ++mi) {
        #pragma unroll
        for (int ni = 0; ni < 4; ++ni) {
            int row = blockIdx.y * BM + mW + mi * 16 + (lane >> 2);
            int col = blockIdx.x * BN + nW + ni * 8 + ((lane & 3) << 1);
            float2 v0 = make_float2(acc[mi][ni][0], acc[mi][ni][1]);
            float2 v1 = make_float2(acc[mi][ni][2], acc[mi][ni][3]);
            *(float2*)&C[(size_t)row * SS + col]       = v0;
            *(float2*)&C[(size_t)(row + 8) * SS + col] = v1;
        }
    }
    #undef LOAD_STAGE
}

// ---------------------------------------------------------------------------
// Masked softmax over rows of 1024, in-place on C (= d_out).
// ---------------------------------------------------------------------------
__global__ void __launch_bounds__(256)
softmax_kernel(float* __restrict__ C, const int* __restrict__ mask,
               const float* __restrict__ bcp)
{
    const size_t row = blockIdx.x;
    float* p = C + row * 1024;
    const int* mp = mask + row * 1024;
    const int t = threadIdx.x;
    const float bias = bcp[0];

    float4 v = ((const float4*)p)[t];
    int4  mk = ((const int4*)mp)[t];

    float x0 = mk.x ? v.x + bias : NEGV;
    float x1 = mk.y ? v.y + bias : NEGV;
    float x2 = mk.z ? v.z + bias : NEGV;
    float x3 = mk.w ? v.w + bias : NEGV;

    float mx = fmaxf(fmaxf(x0, x1), fmaxf(x2, x3));
    #pragma unroll
    for (int o = 16; o; o >>= 1)
        mx = fmaxf(mx, __shfl_xor_sync(0xffffffffu, mx, o));

    __shared__ float red_m[8];
    __shared__ float red_s[8];
    if ((t & 31) == 0) red_m[t >> 5] = mx;
    __syncthreads();
    mx = red_m[0];
    #pragma unroll
    for (int i = 1; i < 8; ++i) mx = fmaxf(mx, red_m[i]);

    float e0 = expf(x0 - mx);
    float e1 = expf(x1 - mx);
    float e2 = expf(x2 - mx);
    float e3 = expf(x3 - mx);
    float s = e0 + e1 + e2 + e3;
    #pragma unroll
    for (int o = 16; o; o >>= 1)
        s += __shfl_xor_sync(0xffffffffu, s, o);
    if ((t & 31) == 0) red_s[t >> 5] = s;
    __syncthreads();
    float tot = red_s[0];
    #pragma unroll
    for (int i = 1; i < 8; ++i) tot += red_s[i];

    const float inv = 1.0f / tot;
    v.x = e0 * inv; v.y = e1 * inv; v.z = e2 * inv; v.w = e3 * inv;
    ((float4*)p)[t] = v;
}

// ---------------------------------------------------------------------------
// Launch
// ---------------------------------------------------------------------------
extern "C" void kernel_launch(void* const* d_in, const int* in_sizes, int n_in,
                              void* d_out, int out_size)
{
    const float* query = (const float*)d_in[0];
    const float* key   = (const float*)d_in[1];
    const int*   mask  = (const int*)  d_in[2];
    const float* Wq    = (const float*)d_in[3];
    const float* bq    = (const float*)d_in[4];
    const float* Wk    = (const float*)d_in[5];
    const float* bk    = (const float*)d_in[6];
    const float* Wc    = (const float*)d_in[7];
    const float* bc    = (const float*)d_in[8];
    float* out = (float*)d_out;

    __half *qc, *kc;
    cudaGetSymbolAddress((void**)&qc, g_Qc);
    cudaGetSymbolAddress((void**)&kc, g_Kc);

    const int smemBytes = 3 * (128 + 128) * 40 * 2;   // 61440
    cudaFuncSetAttribute(gemm_fp16_nt,
                         cudaFuncAttributeMaxDynamicSharedMemorySize, smemBytes);

    // Q slabs: [hi | lo]; K slabs: [hi | hi]  -> (Qhi+Qlo)·Khi = q·Khi
    proj2_kernel<<<2048, 256>>>(query, key, Wq, bq, Wk, bk, Wc, qc, kc);

    // comb[b] = Qc[b] @ Kc[b]^T  (K=2048)
    gemm_fp16_nt<<<dim3(8, 8, 4), 256, smemBytes>>>(qc, kc, out);

    // mask + softmax, in-place
    softmax_kernel<<<BB * SS, 256>>>(out, mask, bc);
}

// round 9
// speedup vs baseline: 2.4731x; 1.2404x over previous
#include <cuda_runtime.h>
#include <cuda_fp16.h>
#include <math.h>
#include <stdint.h>

// Problem constants: B=4, S=1024, D=1024, H=16, DK=64
#define BB 4
#define SS 1024
#define HH 16
#define KC 2048          // Q slabs: [hi|lo].  K: single slab of 1024 (reused)
#define NEGV -10000000000.0f

// Scratch: Qc 16MB ([hi|lo]), Kc 8MB (hi only; GEMM reads it twice).
__device__ __half g_Qc[(size_t)BB * SS * KC];
__device__ __half g_Kc[(size_t)BB * SS * 1024];

// ---------------------------------------------------------------------------
// Projection: blocks 0..1023 -> Q path, 1024..2047 -> K path.
// Register-resident W row per thread (d = t&63), smem-staged x rows,
// broadcast float4 reads, 4 accumulators, single __syncthreads.
// Q: out[base]=hi, out[base+1024]=lo (stride 2048).
// K: out[base]=hi only            (stride 1024).
// ---------------------------------------------------------------------------
__global__ void __launch_bounds__(256)
proj2_kernel(const float* __restrict__ qin, const float* __restrict__ kin,
             const float* __restrict__ Wq, const float* __restrict__ bq,
             const float* __restrict__ Wk, const float* __restrict__ bk,
             const float* __restrict__ Wc,
             __half* __restrict__ qc, __half* __restrict__ kc)
{
    const bool isQ = blockIdx.x < 1024;
    const float* x    = isQ ? qin : kin;
    const float* W    = isQ ? Wq : Wk;
    const float* bias = isQ ? bq : bk;
    __half* out = isQ ? qc : kc;
    const int outStride = isQ ? KC : 1024;
    const int blk = blockIdx.x & 1023;

    __shared__ float xs[64][64];            // 16KB: this block's 64 input rows

    const int t  = threadIdx.x;
    const int d  = t & 63;
    const int tg = t >> 6;                  // 0..3: row group (16 rows each)

    // Stage x: 64 rows x 64 floats = 1024 float4, 256 threads x 4
    const float4* xg = (const float4*)(x + (size_t)blk * 64 * 64);
    float4* xsv = (float4*)&xs[0][0];
    #pragma unroll
    for (int i = 0; i < 4; ++i)
        xsv[t + i * 256] = xg[t + i * 256];

    // W row for this thread's output column d -> registers
    float wr[64];
    {
        const float4* W4 = (const float4*)(W + d * 64);
        #pragma unroll
        for (int i = 0; i < 16; ++i) {
            float4 wv = W4[i];
            wr[4 * i + 0] = wv.x; wr[4 * i + 1] = wv.y;
            wr[4 * i + 2] = wv.z; wr[4 * i + 3] = wv.w;
        }
    }
    const float bv = bias[d];
    const int rowBase = blk * 64;           // global row = (b*H + h)*1024 + i
    const int h  = (rowBase >> 10) & (HH - 1);
    const float scale = isQ ? Wc[h] : 1.0f;
    __syncthreads();

    #pragma unroll 4
    for (int rr = 0; rr < 16; ++rr) {
        const int row = tg * 16 + rr;
        const float4* xr = (const float4*)&xs[row][0];
        float a0 = 0.f, a1 = 0.f, a2 = 0.f, a3 = 0.f;
        #pragma unroll
        for (int i = 0; i < 16; ++i) {
            float4 xv = xr[i];
            a0 = fmaf(wr[4 * i + 0], xv.x, a0);
            a1 = fmaf(wr[4 * i + 1], xv.y, a1);
            a2 = fmaf(wr[4 * i + 2], xv.z, a2);
            a3 = fmaf(wr[4 * i + 3], xv.w, a3);
        }
        const float val = tanhf((a0 + a1) + (a2 + a3) + bv) * scale;
        const __half hi = __float2half(val);

        const int rg = rowBase + row;
        const int i  = rg & 1023;
        const int bb = rg >> 14;
        size_t base = (size_t)((bb << 10) + i) * outStride + h * 64 + d;
        out[base] = hi;
        if (isQ)
            out[base + 1024] = __float2half(val - __half2float(hi));
    }
}

// ---------------------------------------------------------------------------
// fp16 NT GEMM: C[b] = A[b](1024x2048) * B[b](1024x1024, read twice)^T.
// 128x128 tile, BK=32, 256 threads (2x4 warps, 64x32 warp tiles),
// mma.sync m16n8k16.f16, 3-stage cp.async pipeline, ldmatrix loads.
// A k-index walks 0..2047; B k-index walks (k & 1023) -> [hi|hi] virtually.
// ---------------------------------------------------------------------------
__global__ void __launch_bounds__(256, 2)
gemm_fp16_nt(const __half* __restrict__ A,
             const __half* __restrict__ B,
             float* __restrict__ C)
{
    constexpr int BM = 128, BN = 128, BK = 32, LDS = 40, NSTAGE = 3;
    constexpr int KTILES = KC / BK;              // 64
    extern __shared__ __half sh[];

    const int t    = threadIdx.x;
    const int lane = t & 31;
    const int warp = t >> 5;
    const int wm   = warp & 1;
    const int wn   = warp >> 1;
    const int mW   = wm * 64;
    const int nW   = wn * 32;
    const int quad = lane >> 3;
    const int l7   = lane & 7;

    A += (size_t)blockIdx.z * SS * KC   + (size_t)blockIdx.y * BM * KC;
    B += (size_t)blockIdx.z * SS * 1024 + (size_t)blockIdx.x * BN * 1024;
    C += (size_t)blockIdx.z * SS * SS;

    const uint32_t sbase = (uint32_t)__cvta_generic_to_shared(sh);
    const uint32_t stageBytes = (uint32_t)(BM + BN) * LDS * 2;
    const uint32_t bOffBytes  = (uint32_t)BM * LDS * 2;

    // staging: each thread copies 2x16B of A and 2x16B of B per stage
    const int rS = t >> 2;          // 0..63
    const int cS = (t & 3) * 8;     // k offset: 0,8,16,24
    const __half* gA0 = A + (size_t)rS * KC + cS;
    const __half* gA1 = A + (size_t)(rS + 64) * KC + cS;
    const __half* gB0 = B + (size_t)rS * 1024 + cS;
    const __half* gB1 = B + (size_t)(rS + 64) * 1024 + cS;
    const uint32_t dA0 = (uint32_t)(rS * LDS + cS) * 2;
    const uint32_t dA1 = (uint32_t)((rS + 64) * LDS + cS) * 2;

    #define LOAD_STAGE(kt, s)                                                   \
    do {                                                                        \
        uint32_t sb = sbase + (uint32_t)(s) * stageBytes;                       \
        int ko  = (kt) * BK;                                                    \
        int kob = ko & 1023;                                                    \
        asm volatile("cp.async.cg.shared.global [%0], [%1], 16;" ::             \
            "r"(sb + dA0), "l"(gA0 + ko));                                      \
        asm volatile("cp.async.cg.shared.global [%0], [%1], 16;" ::             \
            "r"(sb + dA1), "l"(gA1 + ko));                                      \
        asm volatile("cp.async.cg.shared.global [%0], [%1], 16;" ::             \
            "r"(sb + bOffBytes + dA0), "l"(gB0 + kob));                         \
        asm volatile("cp.async.cg.shared.global [%0], [%1], 16;" ::             \
            "r"(sb + bOffBytes + dA1), "l"(gB1 + kob));                         \
    } while (0)

    float acc[4][4][4];
    #pragma unroll
    for (int mi = 0; mi < 4; ++mi)
        #pragma unroll
        for (int ni = 0; ni < 4; ++ni)
            #pragma unroll
            for (int r = 0; r < 4; ++r) acc[mi][ni][r] = 0.0f;

    const int aRow  = mW + ((quad & 1) << 3) + l7;
    const int aKoff = (quad >> 1) << 3;
    const int bRowQ = ((quad >> 1) << 3) + l7;
    const int bKoff = (quad & 1) << 3;

    LOAD_STAGE(0, 0);
    asm volatile("cp.async.commit_group;");
    LOAD_STAGE(1, 1);
    asm volatile("cp.async.commit_group;");
    asm volatile("cp.async.wait_group 1;");
    __syncthreads();

    for (int kt = 0; kt < KTILES; ++kt) {
        if (kt + 2 < KTILES) {
            LOAD_STAGE(kt + 2, (kt + 2) % NSTAGE);
        }
        asm volatile("cp.async.commit_group;");

        const uint32_t sA = sbase + (uint32_t)(kt % NSTAGE) * stageBytes;
        const uint32_t sB = sA + bOffBytes;

        #pragma unroll
        for (int ks = 0; ks < 2; ++ks) {
            uint32_t ar[4][4];
            #pragma unroll
            for (int mi = 0; mi < 4; ++mi) {
                uint32_t addr = sA +
                    (uint32_t)((aRow + mi * 16) * LDS + ks * 16 + aKoff) * 2;
                asm volatile(
                    "ldmatrix.sync.aligned.m8n8.x4.shared.b16 {%0,%1,%2,%3}, [%4];"
                    : "=r"(ar[mi][0]), "=r"(ar[mi][1]),
                      "=r"(ar[mi][2]), "=r"(ar[mi][3])
                    : "r"(addr));
            }
            uint32_t br[4][2];
            #pragma unroll
            for (int p = 0; p < 2; ++p) {
                uint32_t addr = sB +
                    (uint32_t)((nW + p * 16 + bRowQ) * LDS + ks * 16 + bKoff) * 2;
                uint32_t r0, r1, r2, r3;
                asm volatile(
                    "ldmatrix.sync.aligned.m8n8.x4.shared.b16 {%0,%1,%2,%3}, [%4];"
                    : "=r"(r0), "=r"(r1), "=r"(r2), "=r"(r3)
                    : "r"(addr));
                br[2 * p][0]     = r0; br[2 * p][1]     = r1;
                br[2 * p + 1][0] = r2; br[2 * p + 1][1] = r3;
            }
            #pragma unroll
            for (int mi = 0; mi < 4; ++mi)
                #pragma unroll
                for (int ni = 0; ni < 4; ++ni)
                    asm volatile(
                        "mma.sync.aligned.m16n8k16.row.col.f32.f16.f16.f32 "
                        "{%0,%1,%2,%3}, {%4,%5,%6,%7}, {%8,%9}, {%0,%1,%2,%3};"
                        : "+f"(acc[mi][ni][0]), "+f"(acc[mi][ni][1]),
                          "+f"(acc[mi][ni][2]), "+f"(acc[mi][ni][3])
                        : "r"(ar[mi][0]), "r"(ar[mi][1]),
                          "r"(ar[mi][2]), "r"(ar[mi][3]),
                          "r"(br[ni][0]), "r"(br[ni][1]));
        }

        asm volatile("cp.async.wait_group 1;");
        __syncthreads();
    }

    // epilogue: write fp32 C
    #pragma unroll
    for (int mi = 0; mi < 4; ++mi) {
        #pragma unroll
        for (int ni = 0; ni < 4; ++ni) {
            int row = blockIdx.y * BM + mW + mi * 16 + (lane >> 2);
            int col = blockIdx.x * BN + nW + ni * 8 + ((lane & 3) << 1);
            float2 v0 = make_float2(acc[mi][ni][0], acc[mi][ni][1]);
            float2 v1 = make_float2(acc[mi][ni][2], acc[mi][ni][3]);
            *(float2*)&C[(size_t)row * SS + col]       = v0;
            *(float2*)&C[(size_t)(row + 8) * SS + col] = v1;
        }
    }
    #undef LOAD_STAGE
}

// ---------------------------------------------------------------------------
// Masked softmax over rows of 1024, in-place on C (= d_out).
// ---------------------------------------------------------------------------
__global__ void __launch_bounds__(256)
softmax_kernel(float* __restrict__ C, const int* __restrict__ mask,
               const float* __restrict__ bcp)
{
    const size_t row = blockIdx.x;
    float* p = C + row * 1024;
    const int* mp = mask + row * 1024;
    const int t = threadIdx.x;
    const float bias = bcp[0];

    float4 v = ((const float4*)p)[t];
    int4  mk = ((const int4*)mp)[t];

    float x0 = mk.x ? v.x + bias : NEGV;
    float x1 = mk.y ? v.y + bias : NEGV;
    float x2 = mk.z ? v.z + bias : NEGV;
    float x3 = mk.w ? v.w + bias : NEGV;

    float mx = fmaxf(fmaxf(x0, x1), fmaxf(x2, x3));
    #pragma unroll
    for (int o = 16; o; o >>= 1)
        mx = fmaxf(mx, __shfl_xor_sync(0xffffffffu, mx, o));

    __shared__ float red_m[8];
    __shared__ float red_s[8];
    if ((t & 31) == 0) red_m[t >> 5] = mx;
    __syncthreads();
    mx = red_m[0];
    #pragma unroll
    for (int i = 1; i < 8; ++i) mx = fmaxf(mx, red_m[i]);

    float e0 = expf(x0 - mx);
    float e1 = expf(x1 - mx);
    float e2 = expf(x2 - mx);
    float e3 = expf(x3 - mx);
    float s = e0 + e1 + e2 + e3;
    #pragma unroll
    for (int o = 16; o; o >>= 1)
        s += __shfl_xor_sync(0xffffffffu, s, o);
    if ((t & 31) == 0) red_s[t >> 5] = s;
    __syncthreads();
    float tot = red_s[0];
    #pragma unroll
    for (int i = 1; i < 8; ++i) tot += red_s[i];

    const float inv = 1.0f / tot;
    v.x = e0 * inv; v.y = e1 * inv; v.z = e2 * inv; v.w = e3 * inv;
    ((float4*)p)[t] = v;
}

// ---------------------------------------------------------------------------
// Launch
// ---------------------------------------------------------------------------
extern "C" void kernel_launch(void* const* d_in, const int* in_sizes, int n_in,
                              void* d_out, int out_size)
{
    const float* query = (const float*)d_in[0];
    const float* key   = (const float*)d_in[1];
    const int*   mask  = (const int*)  d_in[2];
    const float* Wq    = (const float*)d_in[3];
    const float* bq    = (const float*)d_in[4];
    const float* Wk    = (const float*)d_in[5];
    const float* bk    = (const float*)d_in[6];
    const float* Wc    = (const float*)d_in[7];
    const float* bc    = (const float*)d_in[8];
    float* out = (float*)d_out;

    __half *qc, *kc;
    cudaGetSymbolAddress((void**)&qc, g_Qc);
    cudaGetSymbolAddress((void**)&kc, g_Kc);

    const int smemBytes = 3 * (128 + 128) * 40 * 2;   // 61440
    cudaFuncSetAttribute(gemm_fp16_nt,
                         cudaFuncAttributeMaxDynamicSharedMemorySize, smemBytes);

    // Q: [hi | lo] (stride 2048); K: hi only (stride 1024, GEMM reads twice)
    proj2_kernel<<<2048, 256>>>(query, key, Wq, bq, Wk, bk, Wc, qc, kc);

    // comb[b] = Qc[b] @ Kc[b]^T  ((Qhi+Qlo)·Khi over virtual K=2048)
    gemm_fp16_nt<<<dim3(8, 8, 4), 256, smemBytes>>>(qc, kc, out);

    // mask + softmax, in-place
    softmax_kernel<<<BB * SS, 256>>>(out, mask, bc);
}

// round 11
// speedup vs baseline: 3.6315x; 1.4684x over previous
#include <cuda_runtime.h>
#include <cuda_fp16.h>
#include <math.h>
#include <stdint.h>

// Problem constants: B=4, S=1024, D=1024, H=16, DK=64
#define BB 4
#define SS 1024
#define HH 16
#define KC 2048          // Q slabs: [hi|lo].  K: single slab of 1024 (reused)
#define NEGV -10000000000.0f

// Scratch: Qc 16MB ([hi|lo]), Kc 8MB (hi only; GEMM reads it twice).
__device__ __half g_Qc[(size_t)BB * SS * KC];
__device__ __half g_Kc[(size_t)BB * SS * 1024];

__device__ __forceinline__ uint32_t packh2(__half a, __half b) {
    __half2 h = __halves2half2(a, b);
    return *(uint32_t*)&h;
}

// ---------------------------------------------------------------------------
// Tensor-core projection. Grid: 1024 blocks; blocks 0..511 -> Q, 512..1023 -> K.
// Each block: 128 rows of one (b,h) slab.  P = X @ W^T + bias, val=tanh(P)*scale.
// fp16 split: virtual K=192: A=[Xhi|Xlo|Xhi], B=[Whi|Whi|Wlo]
//   => X@Whi + Xhi@Wlo  (drops only Xlo@Wlo ~ 2^-24).
// smem: Xs 128x136 halves ([Xhi|Xlo]+pad), Wsm 64x136 ([Whi|Wlo]+pad), bias.
// ---------------------------------------------------------------------------
#define XS_STRIDE 136
#define PROJ_SMEM ((128 + 64) * XS_STRIDE * 2 + 256)

__global__ void __launch_bounds__(256)
proj_mma_kernel(const float* __restrict__ qin, const float* __restrict__ kin,
                const float* __restrict__ Wq, const float* __restrict__ bq,
                const float* __restrict__ Wk, const float* __restrict__ bk,
                const float* __restrict__ Wc,
                __half* __restrict__ qc, __half* __restrict__ kc)
{
    extern __shared__ __half sp[];
    __half* Xs  = sp;                            // 128 x 136
    __half* Wsm = sp + 128 * XS_STRIDE;          // 64 x 136
    float*  bs  = (float*)(sp + (128 + 64) * XS_STRIDE);

    const bool isQ = blockIdx.x < 512;
    const int bid  = blockIdx.x & 511;
    const int slab = bid >> 3;                   // b*16 + h
    const int bis  = bid & 7;                    // 128-row block within slab
    const int b    = slab >> 4;
    const int h    = slab & 15;

    const float* x    = (isQ ? qin : kin) + ((size_t)slab * 1024 + bis * 128) * 64;
    const float* W    = isQ ? Wq : Wk;
    const float* bias = isQ ? bq : bk;
    __half* out = isQ ? qc : kc;
    const int outStride = isQ ? KC : 1024;
    const float scale = isQ ? Wc[h] : 1.0f;

    const int t = threadIdx.x;
    if (t < 64) bs[t] = bias[t];

    // Stage X tile (128x64 fp32) -> Xs as [hi|lo] fp16
    {
        const int r  = t >> 1;
        const int cs = (t & 1) * 32;
        const float4* xg = (const float4*)(x + r * 64 + cs);
        #pragma unroll
        for (int i = 0; i < 8; ++i) {
            float4 v = xg[i];
            __half hx = __float2half(v.x), hy = __float2half(v.y);
            __half hz = __float2half(v.z), hw = __float2half(v.w);
            uint2 hiv, lov;
            hiv.x = packh2(hx, hy);
            hiv.y = packh2(hz, hw);
            lov.x = packh2(__float2half(v.x - __half2float(hx)),
                           __float2half(v.y - __half2float(hy)));
            lov.y = packh2(__float2half(v.z - __half2float(hz)),
                           __float2half(v.w - __half2float(hw)));
            *(uint2*)&Xs[r * XS_STRIDE + cs + 4 * i]      = hiv;
            *(uint2*)&Xs[r * XS_STRIDE + 64 + cs + 4 * i] = lov;
        }
    }
    // Stage W (64x64 fp32) -> Wsm as [hi|lo]
    {
        const int d   = t >> 2;
        const int seg = (t & 3) * 16;
        const float4* wg = (const float4*)(W + d * 64 + seg);
        #pragma unroll
        for (int i = 0; i < 4; ++i) {
            float4 v = wg[i];
            __half hx = __float2half(v.x), hy = __float2half(v.y);
            __half hz = __float2half(v.z), hw = __float2half(v.w);
            uint2 hiv, lov;
            hiv.x = packh2(hx, hy);
            hiv.y = packh2(hz, hw);
            lov.x = packh2(__float2half(v.x - __half2float(hx)),
                           __float2half(v.y - __half2float(hy)));
            lov.y = packh2(__float2half(v.z - __half2float(hz)),
                           __float2half(v.w - __half2float(hw)));
            *(uint2*)&Wsm[d * XS_STRIDE + seg + 4 * i]      = hiv;
            *(uint2*)&Wsm[d * XS_STRIDE + 64 + seg + 4 * i] = lov;
        }
    }
    __syncthreads();

    const int lane = t & 31, warp = t >> 5;
    const int quad = lane >> 3, l7 = lane & 7;
    const uint32_t sX = (uint32_t)__cvta_generic_to_shared(Xs);
    const uint32_t sW = (uint32_t)__cvta_generic_to_shared(Wsm);

    const int aRow = warp * 16 + ((quad & 1) << 3) + l7;   // A fragment row
    const int aK   = (quad >> 1) << 3;
    const int bRow = ((quad >> 1) << 3) + l7;              // B fragment row (n)
    const int bK   = (quad & 1) << 3;

    float acc[8][4];
    #pragma unroll
    for (int ni = 0; ni < 8; ++ni)
        #pragma unroll
        for (int j = 0; j < 4; ++j) acc[ni][j] = 0.0f;

    #pragma unroll
    for (int ks = 0; ks < 12; ++ks) {
        const int a_off = (ks < 8) ? ((ks & 3) * 16 + (ks >> 2) * 64)
                                   : ((ks - 8) * 16);
        const int b_off = (ks < 8) ? ((ks & 3) * 16)
                                   : (64 + (ks - 8) * 16);
        uint32_t a0, a1, a2, a3;
        {
            uint32_t addr = sX + (uint32_t)(aRow * XS_STRIDE + a_off + aK) * 2;
            asm volatile(
                "ldmatrix.sync.aligned.m8n8.x4.shared.b16 {%0,%1,%2,%3}, [%4];"
                : "=r"(a0), "=r"(a1), "=r"(a2), "=r"(a3) : "r"(addr));
        }
        uint32_t br[8][2];
        #pragma unroll
        for (int p = 0; p < 4; ++p) {
            uint32_t addr = sW +
                (uint32_t)((p * 16 + bRow) * XS_STRIDE + b_off + bK) * 2;
            uint32_t r0, r1, r2, r3;
            asm volatile(
                "ldmatrix.sync.aligned.m8n8.x4.shared.b16 {%0,%1,%2,%3}, [%4];"
                : "=r"(r0), "=r"(r1), "=r"(r2), "=r"(r3) : "r"(addr));
            br[2 * p][0]     = r0; br[2 * p][1]     = r1;
            br[2 * p + 1][0] = r2; br[2 * p + 1][1] = r3;
        }
        #pragma unroll
        for (int ni = 0; ni < 8; ++ni)
            asm volatile(
                "mma.sync.aligned.m16n8k16.row.col.f32.f16.f16.f32 "
                "{%0,%1,%2,%3}, {%4,%5,%6,%7}, {%8,%9}, {%0,%1,%2,%3};"
                : "+f"(acc[ni][0]), "+f"(acc[ni][1]),
                  "+f"(acc[ni][2]), "+f"(acc[ni][3])
                : "r"(a0), "r"(a1), "r"(a2), "r"(a3),
                  "r"(br[ni][0]), "r"(br[ni][1]));
    }

    // Epilogue: bias + tanh + scale, hi/lo split, half2 stores
    const int i0 = bis * 128 + warp * 16 + (lane >> 2);   // row within slab
    const int cb = (lane & 3) * 2;
    const size_t base0 = (size_t)((b << 10) + i0)     * outStride + h * 64;
    const size_t base1 = (size_t)((b << 10) + i0 + 8) * outStride + h * 64;

    #pragma unroll
    for (int ni = 0; ni < 8; ++ni) {
        const int c = ni * 8 + cb;
        const float bv0 = bs[c], bv1 = bs[c + 1];

        float v0 = tanhf(acc[ni][0] + bv0) * scale;
        float v1 = tanhf(acc[ni][1] + bv1) * scale;
        __half h0 = __float2half(v0), h1 = __float2half(v1);
        *(uint32_t*)&out[base0 + c] = packh2(h0, h1);
        if (isQ) {
            *(uint32_t*)&out[base0 + 1024 + c] =
                packh2(__float2half(v0 - __half2float(h0)),
                       __float2half(v1 - __half2float(h1)));
        }

        float v2 = tanhf(acc[ni][2] + bv0) * scale;
        float v3 = tanhf(acc[ni][3] + bv1) * scale;
        __half h2 = __float2half(v2), h3 = __float2half(v3);
        *(uint32_t*)&out[base1 + c] = packh2(h2, h3);
        if (isQ) {
            *(uint32_t*)&out[base1 + 1024 + c] =
                packh2(__float2half(v2 - __half2float(h2)),
                       __float2half(v3 - __half2float(h3)));
        }
    }
}

// ---------------------------------------------------------------------------
// fp16 NT GEMM: C[b] = A[b](1024x2048) * B[b](1024x1024, read twice)^T.
// 128x128 tile, BK=32, 256 threads, mma.sync m16n8k16, 3-stage cp.async.
// ---------------------------------------------------------------------------
__global__ void __launch_bounds__(256, 2)
gemm_fp16_nt(const __half* __restrict__ A,
             const __half* __restrict__ B,
             float* __restrict__ C)
{
    constexpr int BM = 128, BN = 128, BK = 32, LDS = 40, NSTAGE = 3;
    constexpr int KTILES = KC / BK;              // 64
    extern __shared__ __half sh[];

    const int t    = threadIdx.x;
    const int lane = t & 31;
    const int warp = t >> 5;
    const int wm   = warp & 1;
    const int wn   = warp >> 1;
    const int mW   = wm * 64;
    const int nW   = wn * 32;
    const int quad = lane >> 3;
    const int l7   = lane & 7;

    A += (size_t)blockIdx.z * SS * KC   + (size_t)blockIdx.y * BM * KC;
    B += (size_t)blockIdx.z * SS * 1024 + (size_t)blockIdx.x * BN * 1024;
    C += (size_t)blockIdx.z * SS * SS;

    const uint32_t sbase = (uint32_t)__cvta_generic_to_shared(sh);
    const uint32_t stageBytes = (uint32_t)(BM + BN) * LDS * 2;
    const uint32_t bOffBytes  = (uint32_t)BM * LDS * 2;

    const int rS = t >> 2;
    const int cS = (t & 3) * 8;
    const __half* gA0 = A + (size_t)rS * KC + cS;
    const __half* gA1 = A + (size_t)(rS + 64) * KC + cS;
    const __half* gB0 = B + (size_t)rS * 1024 + cS;
    const __half* gB1 = B + (size_t)(rS + 64) * 1024 + cS;
    const uint32_t dA0 = (uint32_t)(rS * LDS + cS) * 2;
    const uint32_t dA1 = (uint32_t)((rS + 64) * LDS + cS) * 2;

    #define LOAD_STAGE(kt, s)                                                   \
    do {                                                                        \
        uint32_t sb = sbase + (uint32_t)(s) * stageBytes;                       \
        int ko  = (kt) * BK;                                                    \
        int kob = ko & 1023;                                                    \
        asm volatile("cp.async.cg.shared.global [%0], [%1], 16;" ::             \
            "r"(sb + dA0), "l"(gA0 + ko));                                      \
        asm volatile("cp.async.cg.shared.global [%0], [%1], 16;" ::             \
            "r"(sb + dA1), "l"(gA1 + ko));                                      \
        asm volatile("cp.async.cg.shared.global [%0], [%1], 16;" ::             \
            "r"(sb + bOffBytes + dA0), "l"(gB0 + kob));                         \
        asm volatile("cp.async.cg.shared.global [%0], [%1], 16;" ::             \
            "r"(sb + bOffBytes + dA1), "l"(gB1 + kob));                         \
    } while (0)

    float acc[4][4][4];
    #pragma unroll
    for (int mi = 0; mi < 4; ++mi)
        #pragma unroll
        for (int ni = 0; ni < 4; ++ni)
            #pragma unroll
            for (int r = 0; r < 4; ++r) acc[mi][ni][r] = 0.0f;

    const int aRow  = mW + ((quad & 1) << 3) + l7;
    const int aKoff = (quad >> 1) << 3;
    const int bRowQ = ((quad >> 1) << 3) + l7;
    const int bKoff = (quad & 1) << 3;

    LOAD_STAGE(0, 0);
    asm volatile("cp.async.commit_group;");
    LOAD_STAGE(1, 1);
    asm volatile("cp.async.commit_group;");
    asm volatile("cp.async.wait_group 1;");
    __syncthreads();

    for (int kt = 0; kt < KTILES; ++kt) {
        if (kt + 2 < KTILES) {
            LOAD_STAGE(kt + 2, (kt + 2) % NSTAGE);
        }
        asm volatile("cp.async.commit_group;");

        const uint32_t sA = sbase + (uint32_t)(kt % NSTAGE) * stageBytes;
        const uint32_t sB = sA + bOffBytes;

        #pragma unroll
        for (int ks = 0; ks < 2; ++ks) {
            uint32_t ar[4][4];
            #pragma unroll
            for (int mi = 0; mi < 4; ++mi) {
                uint32_t addr = sA +
                    (uint32_t)((aRow + mi * 16) * LDS + ks * 16 + aKoff) * 2;
                asm volatile(
                    "ldmatrix.sync.aligned.m8n8.x4.shared.b16 {%0,%1,%2,%3}, [%4];"
                    : "=r"(ar[mi][0]), "=r"(ar[mi][1]),
                      "=r"(ar[mi][2]), "=r"(ar[mi][3])
                    : "r"(addr));
            }
            uint32_t br[4][2];
            #pragma unroll
            for (int p = 0; p < 2; ++p) {
                uint32_t addr = sB +
                    (uint32_t)((nW + p * 16 + bRowQ) * LDS + ks * 16 + bKoff) * 2;
                uint32_t r0, r1, r2, r3;
                asm volatile(
                    "ldmatrix.sync.aligned.m8n8.x4.shared.b16 {%0,%1,%2,%3}, [%4];"
                    : "=r"(r0), "=r"(r1), "=r"(r2), "=r"(r3)
                    : "r"(addr));
                br[2 * p][0]     = r0; br[2 * p][1]     = r1;
                br[2 * p + 1][0] = r2; br[2 * p + 1][1] = r3;
            }
            #pragma unroll
            for (int mi = 0; mi < 4; ++mi)
                #pragma unroll
                for (int ni = 0; ni < 4; ++ni)
                    asm volatile(
                        "mma.sync.aligned.m16n8k16.row.col.f32.f16.f16.f32 "
                        "{%0,%1,%2,%3}, {%4,%5,%6,%7}, {%8,%9}, {%0,%1,%2,%3};"
                        : "+f"(acc[mi][ni][0]), "+f"(acc[mi][ni][1]),
                          "+f"(acc[mi][ni][2]), "+f"(acc[mi][ni][3])
                        : "r"(ar[mi][0]), "r"(ar[mi][1]),
                          "r"(ar[mi][2]), "r"(ar[mi][3]),
                          "r"(br[ni][0]), "r"(br[ni][1]));
        }

        asm volatile("cp.async.wait_group 1;");
        __syncthreads();
    }

    #pragma unroll
    for (int mi = 0; mi < 4; ++mi) {
        #pragma unroll
        for (int ni = 0; ni < 4; ++ni) {
            int row = blockIdx.y * BM + mW + mi * 16 + (lane >> 2);
            int col = blockIdx.x * BN + nW + ni * 8 + ((lane & 3) << 1);
            float2 v0 = make_float2(acc[mi][ni][0], acc[mi][ni][1]);
            float2 v1 = make_float2(acc[mi][ni][2], acc[mi][ni][3]);
            *(float2*)&C[(size_t)row * SS + col]       = v0;
            *(float2*)&C[(size_t)(row + 8) * SS + col] = v1;
        }
    }
    #undef LOAD_STAGE
}

// ---------------------------------------------------------------------------
// Masked softmax over rows of 1024, in-place on C (= d_out).
// ---------------------------------------------------------------------------
__global__ void __launch_bounds__(256)
softmax_kernel(float* __restrict__ C, const int* __restrict__ mask,
               const float* __restrict__ bcp)
{
    const size_t row = blockIdx.x;
    float* p = C + row * 1024;
    const int* mp = mask + row * 1024;
    const int t = threadIdx.x;
    const float bias = bcp[0];

    float4 v = ((const float4*)p)[t];
    int4  mk = ((const int4*)mp)[t];

    float x0 = mk.x ? v.x + bias : NEGV;
    float x1 = mk.y ? v.y + bias : NEGV;
    float x2 = mk.z ? v.z + bias : NEGV;
    float x3 = mk.w ? v.w + bias : NEGV;

    float mx = fmaxf(fmaxf(x0, x1), fmaxf(x2, x3));
    #pragma unroll
    for (int o = 16; o; o >>= 1)
        mx = fmaxf(mx, __shfl_xor_sync(0xffffffffu, mx, o));

    __shared__ float red_m[8];
    __shared__ float red_s[8];
    if ((t & 31) == 0) red_m[t >> 5] = mx;
    __syncthreads();
    mx = red_m[0];
    #pragma unroll
    for (int i = 1; i < 8; ++i) mx = fmaxf(mx, red_m[i]);

    float e0 = expf(x0 - mx);
    float e1 = expf(x1 - mx);
    float e2 = expf(x2 - mx);
    float e3 = expf(x3 - mx);
    float s = e0 + e1 + e2 + e3;
    #pragma unroll
    for (int o = 16; o; o >>= 1)
        s += __shfl_xor_sync(0xffffffffu, s, o);
    if ((t & 31) == 0) red_s[t >> 5] = s;
    __syncthreads();
    float tot = red_s[0];
    #pragma unroll
    for (int i = 1; i < 8; ++i) tot += red_s[i];

    const float inv = 1.0f / tot;
    v.x = e0 * inv; v.y = e1 * inv; v.z = e2 * inv; v.w = e3 * inv;
    ((float4*)p)[t] = v;
}

// ---------------------------------------------------------------------------
// Launch
// ---------------------------------------------------------------------------
extern "C" void kernel_launch(void* const* d_in, const int* in_sizes, int n_in,
                              void* d_out, int out_size)
{
    const float* query = (const float*)d_in[0];
    const float* key   = (const float*)d_in[1];
    const int*   mask  = (const int*)  d_in[2];
    const float* Wq    = (const float*)d_in[3];
    const float* bq    = (const float*)d_in[4];
    const float* Wk    = (const float*)d_in[5];
    const float* bk    = (const float*)d_in[6];
    const float* Wc    = (const float*)d_in[7];
    const float* bc    = (const float*)d_in[8];
    float* out = (float*)d_out;

    __half *qc, *kc;
    cudaGetSymbolAddress((void**)&qc, g_Qc);
    cudaGetSymbolAddress((void**)&kc, g_Kc);

    const int smemBytes = 3 * (128 + 128) * 40 * 2;   // 61440
    cudaFuncSetAttribute(gemm_fp16_nt,
                         cudaFuncAttributeMaxDynamicSharedMemorySize, smemBytes);
    cudaFuncSetAttribute(proj_mma_kernel,
                         cudaFuncAttributeMaxDynamicSharedMemorySize, PROJ_SMEM);

    // Tensor-core projection: Q -> [hi|lo] (stride 2048); K -> hi (stride 1024)
    proj_mma_kernel<<<1024, 256, PROJ_SMEM>>>(query, key, Wq, bq, Wk, bk, Wc,
                                              qc, kc);

    // comb[b] = Qc[b] @ Kc[b]^T  ((Qhi+Qlo)·Khi over virtual K=2048)
    gemm_fp16_nt<<<dim3(8, 8, 4), 256, smemBytes>>>(qc, kc, out);

    // mask + softmax, in-place
    softmax_kernel<<<BB * SS, 256>>>(out, mask, bc);
}

// round 12
// speedup vs baseline: 5.6125x; 1.5455x over previous
#include <cuda_runtime.h>
#include <cuda_fp16.h>
#include <math.h>
#include <stdint.h>

// Problem constants: B=4, S=1024, D=1024, H=16, DK=64
#define BB 4
#define SS 1024
#define HH 16
#define KC 1024          // single fp16 hi slab for both Q and K
#define NEGV -10000000000.0f

// Scratch: Qc/Kc 8MB each (fp16 hi only).
__device__ __half g_Qc[(size_t)BB * SS * KC];
__device__ __half g_Kc[(size_t)BB * SS * KC];

__device__ __forceinline__ uint32_t packh2(__half a, __half b) {
    __half2 h = __halves2half2(a, b);
    return *(uint32_t*)&h;
}

// ---------------------------------------------------------------------------
// Tensor-core projection. Grid: 1024 blocks; blocks 0..511 -> Q, 512..1023 -> K.
// Each block: 128 rows of one (b,h) slab.  P = X @ W^T + bias, val=tanh(P)*scale.
// Internal fp16 split for fp32-accurate tanh input: virtual K=192:
//   A=[Xhi|Xlo|Xhi], B=[Whi|Whi|Wlo]  => X@Whi + Xhi@Wlo (drops Xlo@Wlo ~2^-24).
// Output: fp16(val) only (quantization error handled by global error budget).
// ---------------------------------------------------------------------------
#define XS_STRIDE 136
#define PROJ_SMEM ((128 + 64) * XS_STRIDE * 2 + 256)

__global__ void __launch_bounds__(256)
proj_mma_kernel(const float* __restrict__ qin, const float* __restrict__ kin,
                const float* __restrict__ Wq, const float* __restrict__ bq,
                const float* __restrict__ Wk, const float* __restrict__ bk,
                const float* __restrict__ Wc,
                __half* __restrict__ qc, __half* __restrict__ kc)
{
    extern __shared__ __half sp[];
    __half* Xs  = sp;                            // 128 x 136
    __half* Wsm = sp + 128 * XS_STRIDE;          // 64 x 136
    float*  bs  = (float*)(sp + (128 + 64) * XS_STRIDE);

    const bool isQ = blockIdx.x < 512;
    const int bid  = blockIdx.x & 511;
    const int slab = bid >> 3;                   // b*16 + h
    const int bis  = bid & 7;                    // 128-row block within slab
    const int b    = slab >> 4;
    const int h    = slab & 15;

    const float* x    = (isQ ? qin : kin) + ((size_t)slab * 1024 + bis * 128) * 64;
    const float* W    = isQ ? Wq : Wk;
    const float* bias = isQ ? bq : bk;
    __half* out = isQ ? qc : kc;
    const float scale = isQ ? Wc[h] : 1.0f;

    const int t = threadIdx.x;
    if (t < 64) bs[t] = bias[t];

    // Stage X tile (128x64 fp32) -> Xs as [hi|lo] fp16
    {
        const int r  = t >> 1;
        const int cs = (t & 1) * 32;
        const float4* xg = (const float4*)(x + r * 64 + cs);
        #pragma unroll
        for (int i = 0; i < 8; ++i) {
            float4 v = xg[i];
            __half hx = __float2half(v.x), hy = __float2half(v.y);
            __half hz = __float2half(v.z), hw = __float2half(v.w);
            uint2 hiv, lov;
            hiv.x = packh2(hx, hy);
            hiv.y = packh2(hz, hw);
            lov.x = packh2(__float2half(v.x - __half2float(hx)),
                           __float2half(v.y - __half2float(hy)));
            lov.y = packh2(__float2half(v.z - __half2float(hz)),
                           __float2half(v.w - __half2float(hw)));
            *(uint2*)&Xs[r * XS_STRIDE + cs + 4 * i]      = hiv;
            *(uint2*)&Xs[r * XS_STRIDE + 64 + cs + 4 * i] = lov;
        }
    }
    // Stage W (64x64 fp32) -> Wsm as [hi|lo]
    {
        const int d   = t >> 2;
        const int seg = (t & 3) * 16;
        const float4* wg = (const float4*)(W + d * 64 + seg);
        #pragma unroll
        for (int i = 0; i < 4; ++i) {
            float4 v = wg[i];
            __half hx = __float2half(v.x), hy = __float2half(v.y);
            __half hz = __float2half(v.z), hw = __float2half(v.w);
            uint2 hiv, lov;
            hiv.x = packh2(hx, hy);
            hiv.y = packh2(hz, hw);
            lov.x = packh2(__float2half(v.x - __half2float(hx)),
                           __float2half(v.y - __half2float(hy)));
            lov.y = packh2(__float2half(v.z - __half2float(hz)),
                           __float2half(v.w - __half2float(hw)));
            *(uint2*)&Wsm[d * XS_STRIDE + seg + 4 * i]      = hiv;
            *(uint2*)&Wsm[d * XS_STRIDE + 64 + seg + 4 * i] = lov;
        }
    }
    __syncthreads();

    const int lane = t & 31, warp = t >> 5;
    const int quad = lane >> 3, l7 = lane & 7;
    const uint32_t sX = (uint32_t)__cvta_generic_to_shared(Xs);
    const uint32_t sW = (uint32_t)__cvta_generic_to_shared(Wsm);

    const int aRow = warp * 16 + ((quad & 1) << 3) + l7;
    const int aK   = (quad >> 1) << 3;
    const int bRow = ((quad >> 1) << 3) + l7;
    const int bK   = (quad & 1) << 3;

    float acc[8][4];
    #pragma unroll
    for (int ni = 0; ni < 8; ++ni)
        #pragma unroll
        for (int j = 0; j < 4; ++j) acc[ni][j] = 0.0f;

    #pragma unroll
    for (int ks = 0; ks < 12; ++ks) {
        const int a_off = (ks < 8) ? ((ks & 3) * 16 + (ks >> 2) * 64)
                                   : ((ks - 8) * 16);
        const int b_off = (ks < 8) ? ((ks & 3) * 16)
                                   : (64 + (ks - 8) * 16);
        uint32_t a0, a1, a2, a3;
        {
            uint32_t addr = sX + (uint32_t)(aRow * XS_STRIDE + a_off + aK) * 2;
            asm volatile(
                "ldmatrix.sync.aligned.m8n8.x4.shared.b16 {%0,%1,%2,%3}, [%4];"
                : "=r"(a0), "=r"(a1), "=r"(a2), "=r"(a3) : "r"(addr));
        }
        uint32_t br[8][2];
        #pragma unroll
        for (int p = 0; p < 4; ++p) {
            uint32_t addr = sW +
                (uint32_t)((p * 16 + bRow) * XS_STRIDE + b_off + bK) * 2;
            uint32_t r0, r1, r2, r3;
            asm volatile(
                "ldmatrix.sync.aligned.m8n8.x4.shared.b16 {%0,%1,%2,%3}, [%4];"
                : "=r"(r0), "=r"(r1), "=r"(r2), "=r"(r3) : "r"(addr));
            br[2 * p][0]     = r0; br[2 * p][1]     = r1;
            br[2 * p + 1][0] = r2; br[2 * p + 1][1] = r3;
        }
        #pragma unroll
        for (int ni = 0; ni < 8; ++ni)
            asm volatile(
                "mma.sync.aligned.m16n8k16.row.col.f32.f16.f16.f32 "
                "{%0,%1,%2,%3}, {%4,%5,%6,%7}, {%8,%9}, {%0,%1,%2,%3};"
                : "+f"(acc[ni][0]), "+f"(acc[ni][1]),
                  "+f"(acc[ni][2]), "+f"(acc[ni][3])
                : "r"(a0), "r"(a1), "r"(a2), "r"(a3),
                  "r"(br[ni][0]), "r"(br[ni][1]));
    }

    // Epilogue: bias + tanh + scale, fp16 stores (hi only)
    const int i0 = bis * 128 + warp * 16 + (lane >> 2);   // row within slab
    const int cb = (lane & 3) * 2;
    const size_t base0 = (size_t)((b << 10) + i0)     * KC + h * 64;
    const size_t base1 = (size_t)((b << 10) + i0 + 8) * KC + h * 64;

    #pragma unroll
    for (int ni = 0; ni < 8; ++ni) {
        const int c = ni * 8 + cb;
        const float bv0 = bs[c], bv1 = bs[c + 1];

        float v0 = tanhf(acc[ni][0] + bv0) * scale;
        float v1 = tanhf(acc[ni][1] + bv1) * scale;
        *(uint32_t*)&out[base0 + c] = packh2(__float2half(v0), __float2half(v1));

        float v2 = tanhf(acc[ni][2] + bv0) * scale;
        float v3 = tanhf(acc[ni][3] + bv1) * scale;
        *(uint32_t*)&out[base1 + c] = packh2(__float2half(v2), __float2half(v3));
    }
}

// ---------------------------------------------------------------------------
// fp16 NT GEMM: C[b] = A[b] * B[b]^T, M=N=K=1024, 4 batches.
// 128x128 tile, BK=32, 256 threads, mma.sync m16n8k16, 3-stage cp.async.
// ---------------------------------------------------------------------------
__global__ void __launch_bounds__(256, 2)
gemm_fp16_nt(const __half* __restrict__ A,
             const __half* __restrict__ B,
             float* __restrict__ C)
{
    constexpr int BM = 128, BN = 128, BK = 32, LDS = 40, NSTAGE = 3;
    constexpr int KTILES = KC / BK;              // 32
    extern __shared__ __half sh[];

    const int t    = threadIdx.x;
    const int lane = t & 31;
    const int warp = t >> 5;
    const int wm   = warp & 1;
    const int wn   = warp >> 1;
    const int mW   = wm * 64;
    const int nW   = wn * 32;
    const int quad = lane >> 3;
    const int l7   = lane & 7;

    A += (size_t)blockIdx.z * SS * KC + (size_t)blockIdx.y * BM * KC;
    B += (size_t)blockIdx.z * SS * KC + (size_t)blockIdx.x * BN * KC;
    C += (size_t)blockIdx.z * SS * SS;

    const uint32_t sbase = (uint32_t)__cvta_generic_to_shared(sh);
    const uint32_t stageBytes = (uint32_t)(BM + BN) * LDS * 2;
    const uint32_t bOffBytes  = (uint32_t)BM * LDS * 2;

    const int rS = t >> 2;
    const int cS = (t & 3) * 8;
    const __half* gA0 = A + (size_t)rS * KC + cS;
    const __half* gA1 = A + (size_t)(rS + 64) * KC + cS;
    const __half* gB0 = B + (size_t)rS * KC + cS;
    const __half* gB1 = B + (size_t)(rS + 64) * KC + cS;
    const uint32_t dA0 = (uint32_t)(rS * LDS + cS) * 2;
    const uint32_t dA1 = (uint32_t)((rS + 64) * LDS + cS) * 2;

    #define LOAD_STAGE(kt, s)                                                   \
    do {                                                                        \
        uint32_t sb = sbase + (uint32_t)(s) * stageBytes;                       \
        int ko = (kt) * BK;                                                     \
        asm volatile("cp.async.cg.shared.global [%0], [%1], 16;" ::             \
            "r"(sb + dA0), "l"(gA0 + ko));                                      \
        asm volatile("cp.async.cg.shared.global [%0], [%1], 16;" ::             \
            "r"(sb + dA1), "l"(gA1 + ko));                                      \
        asm volatile("cp.async.cg.shared.global [%0], [%1], 16;" ::             \
            "r"(sb + bOffBytes + dA0), "l"(gB0 + ko));                          \
        asm volatile("cp.async.cg.shared.global [%0], [%1], 16;" ::             \
            "r"(sb + bOffBytes + dA1), "l"(gB1 + ko));                          \
    } while (0)

    float acc[4][4][4];
    #pragma unroll
    for (int mi = 0; mi < 4; ++mi)
        #pragma unroll
        for (int ni = 0; ni < 4; ++ni)
            #pragma unroll
            for (int r = 0; r < 4; ++r) acc[mi][ni][r] = 0.0f;

    const int aRow  = mW + ((quad & 1) << 3) + l7;
    const int aKoff = (quad >> 1) << 3;
    const int bRowQ = ((quad >> 1) << 3) + l7;
    const int bKoff = (quad & 1) << 3;

    LOAD_STAGE(0, 0);
    asm volatile("cp.async.commit_group;");
    LOAD_STAGE(1, 1);
    asm volatile("cp.async.commit_group;");
    asm volatile("cp.async.wait_group 1;");
    __syncthreads();

    for (int kt = 0; kt < KTILES; ++kt) {
        if (kt + 2 < KTILES) {
            LOAD_STAGE(kt + 2, (kt + 2) % NSTAGE);
        }
        asm volatile("cp.async.commit_group;");

        const uint32_t sA = sbase + (uint32_t)(kt % NSTAGE) * stageBytes;
        const uint32_t sB = sA + bOffBytes;

        #pragma unroll
        for (int ks = 0; ks < 2; ++ks) {
            uint32_t ar[4][4];
            #pragma unroll
            for (int mi = 0; mi < 4; ++mi) {
                uint32_t addr = sA +
                    (uint32_t)((aRow + mi * 16) * LDS + ks * 16 + aKoff) * 2;
                asm volatile(
                    "ldmatrix.sync.aligned.m8n8.x4.shared.b16 {%0,%1,%2,%3}, [%4];"
                    : "=r"(ar[mi][0]), "=r"(ar[mi][1]),
                      "=r"(ar[mi][2]), "=r"(ar[mi][3])
                    : "r"(addr));
            }
            uint32_t br[4][2];
            #pragma unroll
            for (int p = 0; p < 2; ++p) {
                uint32_t addr = sB +
                    (uint32_t)((nW + p * 16 + bRowQ) * LDS + ks * 16 + bKoff) * 2;
                uint32_t r0, r1, r2, r3;
                asm volatile(
                    "ldmatrix.sync.aligned.m8n8.x4.shared.b16 {%0,%1,%2,%3}, [%4];"
                    : "=r"(r0), "=r"(r1), "=r"(r2), "=r"(r3)
                    : "r"(addr));
                br[2 * p][0]     = r0; br[2 * p][1]     = r1;
                br[2 * p + 1][0] = r2; br[2 * p + 1][1] = r3;
            }
            #pragma unroll
            for (int mi = 0; mi < 4; ++mi)
                #pragma unroll
                for (int ni = 0; ni < 4; ++ni)
                    asm volatile(
                        "mma.sync.aligned.m16n8k16.row.col.f32.f16.f16.f32 "
                        "{%0,%1,%2,%3}, {%4,%5,%6,%7}, {%8,%9}, {%0,%1,%2,%3};"
                        : "+f"(acc[mi][ni][0]), "+f"(acc[mi][ni][1]),
                          "+f"(acc[mi][ni][2]), "+f"(acc[mi][ni][3])
                        : "r"(ar[mi][0]), "r"(ar[mi][1]),
                          "r"(ar[mi][2]), "r"(ar[mi][3]),
                          "r"(br[ni][0]), "r"(br[ni][1]));
        }

        asm volatile("cp.async.wait_group 1;");
        __syncthreads();
    }

    #pragma unroll
    for (int mi = 0; mi < 4; ++mi) {
        #pragma unroll
        for (int ni = 0; ni < 4; ++ni) {
            int row = blockIdx.y * BM + mW + mi * 16 + (lane >> 2);
            int col = blockIdx.x * BN + nW + ni * 8 + ((lane & 3) << 1);
            float2 v0 = make_float2(acc[mi][ni][0], acc[mi][ni][1]);
            float2 v1 = make_float2(acc[mi][ni][2], acc[mi][ni][3]);
            *(float2*)&C[(size_t)row * SS + col]       = v0;
            *(float2*)&C[(size_t)(row + 8) * SS + col] = v1;
        }
    }
    #undef LOAD_STAGE
}

// ---------------------------------------------------------------------------
// Masked softmax over rows of 1024, in-place on C (= d_out).
// ---------------------------------------------------------------------------
__global__ void __launch_bounds__(256)
softmax_kernel(float* __restrict__ C, const int* __restrict__ mask,
               const float* __restrict__ bcp)
{
    const size_t row = blockIdx.x;
    float* p = C + row * 1024;
    const int* mp = mask + row * 1024;
    const int t = threadIdx.x;
    const float bias = bcp[0];

    float4 v = ((const float4*)p)[t];
    int4  mk = ((const int4*)mp)[t];

    float x0 = mk.x ? v.x + bias : NEGV;
    float x1 = mk.y ? v.y + bias : NEGV;
    float x2 = mk.z ? v.z + bias : NEGV;
    float x3 = mk.w ? v.w + bias : NEGV;

    float mx = fmaxf(fmaxf(x0, x1), fmaxf(x2, x3));
    #pragma unroll
    for (int o = 16; o; o >>= 1)
        mx = fmaxf(mx, __shfl_xor_sync(0xffffffffu, mx, o));

    __shared__ float red_m[8];
    __shared__ float red_s[8];
    if ((t & 31) == 0) red_m[t >> 5] = mx;
    __syncthreads();
    mx = red_m[0];
    #pragma unroll
    for (int i = 1; i < 8; ++i) mx = fmaxf(mx, red_m[i]);

    float e0 = expf(x0 - mx);
    float e1 = expf(x1 - mx);
    float e2 = expf(x2 - mx);
    float e3 = expf(x3 - mx);
    float s = e0 + e1 + e2 + e3;
    #pragma unroll
    for (int o = 16; o; o >>= 1)
        s += __shfl_xor_sync(0xffffffffu, s, o);
    if ((t & 31) == 0) red_s[t >> 5] = s;
    __syncthreads();
    float tot = red_s[0];
    #pragma unroll
    for (int i = 1; i < 8; ++i) tot += red_s[i];

    const float inv = 1.0f / tot;
    v.x = e0 * inv; v.y = e1 * inv; v.z = e2 * inv; v.w = e3 * inv;
    ((float4*)p)[t] = v;
}

// ---------------------------------------------------------------------------
// Launch
// ---------------------------------------------------------------------------
extern "C" void kernel_launch(void* const* d_in, const int* in_sizes, int n_in,
                              void* d_out, int out_size)
{
    const float* query = (const float*)d_in[0];
    const float* key   = (const float*)d_in[1];
    const int*   mask  = (const int*)  d_in[2];
    const float* Wq    = (const float*)d_in[3];
    const float* bq    = (const float*)d_in[4];
    const float* Wk    = (const float*)d_in[5];
    const float* bk    = (const float*)d_in[6];
    const float* Wc    = (const float*)d_in[7];
    const float* bc    = (const float*)d_in[8];
    float* out = (float*)d_out;

    __half *qc, *kc;
    cudaGetSymbolAddress((void**)&qc, g_Qc);
    cudaGetSymbolAddress((void**)&kc, g_Kc);

    const int smemBytes = 3 * (128 + 128) * 40 * 2;   // 61440
    cudaFuncSetAttribute(gemm_fp16_nt,
                         cudaFuncAttributeMaxDynamicSharedMemorySize, smemBytes);
    cudaFuncSetAttribute(proj_mma_kernel,
                         cudaFuncAttributeMaxDynamicSharedMemorySize, PROJ_SMEM);

    // Tensor-core projection: Q and K -> fp16 hi slabs (stride 1024)
    proj_mma_kernel<<<1024, 256, PROJ_SMEM>>>(query, key, Wq, bq, Wk, bk, Wc,
                                              qc, kc);

    // comb[b] = Qc[b] @ Kc[b]^T  (K=1024)
    gemm_fp16_nt<<<dim3(8, 8, 4), 256, smemBytes>>>(qc, kc, out);

    // mask + softmax, in-place
    softmax_kernel<<<BB * SS, 256>>>(out, mask, bc);
}

// round 15
// speedup vs baseline: 6.0753x; 1.0825x over previous
#include <cuda_runtime.h>
#include <cuda_fp16.h>
#include <math.h>
#include <stdint.h>

// Problem constants: B=4, S=1024, D=1024, H=16, DK=64
#define BB 4
#define SS 1024
#define HH 16
#define KC 1024          // single fp16 hi slab for both Q and K
#define NEGV -10000000000.0f

// Scratch: Qc/Kc 8MB each (fp16).
__device__ __half g_Qc[(size_t)BB * SS * KC];
__device__ __half g_Kc[(size_t)BB * SS * KC];

__device__ __forceinline__ uint32_t packh2(__half a, __half b) {
    __half2 h = __halves2half2(a, b);
    return *(uint32_t*)&h;
}

// ---------------------------------------------------------------------------
// Tensor-core projection, pure fp16 operands (K=64, 4 mma K-steps).
// Grid: 1024 blocks; blocks 0..511 -> Q, 512..1023 -> K.
// Each block: 128 rows of one (b,h) slab.  P = Xhi @ Whi^T (fp32 acc),
// val = tanh(P + bias) * scale, stored fp16.
// ---------------------------------------------------------------------------
#define XS_STRIDE 72
#define PROJ_SMEM ((128 + 64) * XS_STRIDE * 2 + 256)

__global__ void __launch_bounds__(256)
proj_mma_kernel(const float* __restrict__ qin, const float* __restrict__ kin,
                const float* __restrict__ Wq, const float* __restrict__ bq,
                const float* __restrict__ Wk, const float* __restrict__ bk,
                const float* __restrict__ Wc,
                __half* __restrict__ qc, __half* __restrict__ kc)
{
    extern __shared__ __half sp[];
    __half* Xs  = sp;                            // 128 x 72
    __half* Wsm = sp + 128 * XS_STRIDE;          // 64 x 72
    float*  bs  = (float*)(sp + (128 + 64) * XS_STRIDE);

    const bool isQ = blockIdx.x < 512;
    const int bid  = blockIdx.x & 511;
    const int slab = bid >> 3;                   // b*16 + h
    const int bis  = bid & 7;                    // 128-row block within slab
    const int b    = slab >> 4;
    const int h    = slab & 15;

    const float* x    = (isQ ? qin : kin) + ((size_t)slab * 1024 + bis * 128) * 64;
    const float* W    = isQ ? Wq : Wk;
    const float* bias = isQ ? bq : bk;
    __half* out = isQ ? qc : kc;
    const float scale = isQ ? Wc[h] : 1.0f;

    const int t = threadIdx.x;
    if (t < 64) bs[t] = bias[t];

    // Stage X tile (128x64 fp32) -> Xs fp16
    {
        const int r  = t >> 1;
        const int cs = (t & 1) * 32;
        const float4* xg = (const float4*)(x + r * 64 + cs);
        #pragma unroll
        for (int i = 0; i < 8; ++i) {
            float4 v = xg[i];
            uint2 hiv;
            hiv.x = packh2(__float2half(v.x), __float2half(v.y));
            hiv.y = packh2(__float2half(v.z), __float2half(v.w));
            *(uint2*)&Xs[r * XS_STRIDE + cs + 4 * i] = hiv;
        }
    }
    // Stage W (64x64 fp32) -> Wsm fp16
    {
        const int d   = t >> 2;
        const int seg = (t & 3) * 16;
        const float4* wg = (const float4*)(W + d * 64 + seg);
        #pragma unroll
        for (int i = 0; i < 4; ++i) {
            float4 v = wg[i];
            uint2 hiv;
            hiv.x = packh2(__float2half(v.x), __float2half(v.y));
            hiv.y = packh2(__float2half(v.z), __float2half(v.w));
            *(uint2*)&Wsm[d * XS_STRIDE + seg + 4 * i] = hiv;
        }
    }
    __syncthreads();

    const int lane = t & 31, warp = t >> 5;
    const int quad = lane >> 3, l7 = lane & 7;
    const uint32_t sX = (uint32_t)__cvta_generic_to_shared(Xs);
    const uint32_t sW = (uint32_t)__cvta_generic_to_shared(Wsm);

    const int aRow = warp * 16 + ((quad & 1) << 3) + l7;
    const int aK   = (quad >> 1) << 3;
    const int bRow = ((quad >> 1) << 3) + l7;
    const int bK   = (quad & 1) << 3;

    float acc[8][4];
    #pragma unroll
    for (int ni = 0; ni < 8; ++ni)
        #pragma unroll
        for (int j = 0; j < 4; ++j) acc[ni][j] = 0.0f;

    #pragma unroll
    for (int ks = 0; ks < 4; ++ks) {
        const int koff = ks * 16;
        uint32_t a0, a1, a2, a3;
        {
            uint32_t addr = sX + (uint32_t)(aRow * XS_STRIDE + koff + aK) * 2;
            asm volatile(
                "ldmatrix.sync.aligned.m8n8.x4.shared.b16 {%0,%1,%2,%3}, [%4];"
                : "=r"(a0), "=r"(a1), "=r"(a2), "=r"(a3) : "r"(addr));
        }
        uint32_t br[8][2];
        #pragma unroll
        for (int p = 0; p < 4; ++p) {
            uint32_t addr = sW +
                (uint32_t)((p * 16 + bRow) * XS_STRIDE + koff + bK) * 2;
            uint32_t r0, r1, r2, r3;
            asm volatile(
                "ldmatrix.sync.aligned.m8n8.x4.shared.b16 {%0,%1,%2,%3}, [%4];"
                : "=r"(r0), "=r"(r1), "=r"(r2), "=r"(r3) : "r"(addr));
            br[2 * p][0]     = r0; br[2 * p][1]     = r1;
            br[2 * p + 1][0] = r2; br[2 * p + 1][1] = r3;
        }
        #pragma unroll
        for (int ni = 0; ni < 8; ++ni)
            asm volatile(
                "mma.sync.aligned.m16n8k16.row.col.f32.f16.f16.f32 "
                "{%0,%1,%2,%3}, {%4,%5,%6,%7}, {%8,%9}, {%0,%1,%2,%3};"
                : "+f"(acc[ni][0]), "+f"(acc[ni][1]),
                  "+f"(acc[ni][2]), "+f"(acc[ni][3])
                : "r"(a0), "r"(a1), "r"(a2), "r"(a3),
                  "r"(br[ni][0]), "r"(br[ni][1]));
    }

    // Epilogue: bias + tanh + scale, fp16 stores
    const int i0 = bis * 128 + warp * 16 + (lane >> 2);   // row within slab
    const int cb = (lane & 3) * 2;
    const size_t base0 = (size_t)((b << 10) + i0)     * KC + h * 64;
    const size_t base1 = (size_t)((b << 10) + i0 + 8) * KC + h * 64;

    #pragma unroll
    for (int ni = 0; ni < 8; ++ni) {
        const int c = ni * 8 + cb;
        const float bv0 = bs[c], bv1 = bs[c + 1];

        float v0 = tanhf(acc[ni][0] + bv0) * scale;
        float v1 = tanhf(acc[ni][1] + bv1) * scale;
        *(uint32_t*)&out[base0 + c] = packh2(__float2half(v0), __float2half(v1));

        float v2 = tanhf(acc[ni][2] + bv0) * scale;
        float v3 = tanhf(acc[ni][3] + bv1) * scale;
        *(uint32_t*)&out[base1 + c] = packh2(__float2half(v2), __float2half(v3));
    }
}

// ---------------------------------------------------------------------------
// fp16 NT GEMM: C[b] = A[b] * B[b]^T, M=N=K=1024, 4 batches.
// 128x128 tile, BK=32, 256 threads, mma.sync m16n8k16, 3-stage cp.async.
// ---------------------------------------------------------------------------
__global__ void __launch_bounds__(256, 2)
gemm_fp16_nt(const __half* __restrict__ A,
             const __half* __restrict__ B,
             float* __restrict__ C)
{
    constexpr int BM = 128, BN = 128, BK = 32, LDS = 40, NSTAGE = 3;
    constexpr int KTILES = KC / BK;              // 32
    extern __shared__ __half sh[];

    const int t    = threadIdx.x;
    const int lane = t & 31;
    const int warp = t >> 5;
    const int wm   = warp & 1;
    const int wn   = warp >> 1;
    const int mW   = wm * 64;
    const int nW   = wn * 32;
    const int quad = lane >> 3;
    const int l7   = lane & 7;

    A += (size_t)blockIdx.z * SS * KC + (size_t)blockIdx.y * BM * KC;
    B += (size_t)blockIdx.z * SS * KC + (size_t)blockIdx.x * BN * KC;
    C += (size_t)blockIdx.z * SS * SS;

    const uint32_t sbase = (uint32_t)__cvta_generic_to_shared(sh);
    const uint32_t stageBytes = (uint32_t)(BM + BN) * LDS * 2;
    const uint32_t bOffBytes  = (uint32_t)BM * LDS * 2;

    const int rS = t >> 2;
    const int cS = (t & 3) * 8;
    const __half* gA0 = A + (size_t)rS * KC + cS;
    const __half* gA1 = A + (size_t)(rS + 64) * KC + cS;
    const __half* gB0 = B + (size_t)rS * KC + cS;
    const __half* gB1 = B + (size_t)(rS + 64) * KC + cS;
    const uint32_t dA0 = (uint32_t)(rS * LDS + cS) * 2;
    const uint32_t dA1 = (uint32_t)((rS + 64) * LDS + cS) * 2;

    #define LOAD_STAGE(kt, s)                                                   \
    do {                                                                        \
        uint32_t sb = sbase + (uint32_t)(s) * stageBytes;                       \
        int ko = (kt) * BK;                                                     \
        asm volatile("cp.async.cg.shared.global [%0], [%1], 16;" ::             \
            "r"(sb + dA0), "l"(gA0 + ko));                                      \
        asm volatile("cp.async.cg.shared.global [%0], [%1], 16;" ::             \
            "r"(sb + dA1), "l"(gA1 + ko));                                      \
        asm volatile("cp.async.cg.shared.global [%0], [%1], 16;" ::             \
            "r"(sb + bOffBytes + dA0), "l"(gB0 + ko));                          \
        asm volatile("cp.async.cg.shared.global [%0], [%1], 16;" ::             \
            "r"(sb + bOffBytes + dA1), "l"(gB1 + ko));                          \
    } while (0)

    float acc[4][4][4];
    #pragma unroll
    for (int mi = 0; mi < 4; ++mi)
        #pragma unroll
        for (int ni = 0; ni < 4; ++ni)
            #pragma unroll
            for (int r = 0; r < 4; ++r) acc[mi][ni][r] = 0.0f;

    const int aRow  = mW + ((quad & 1) << 3) + l7;
    const int aKoff = (quad >> 1) << 3;
    const int bRowQ = ((quad >> 1) << 3) + l7;
    const int bKoff = (quad & 1) << 3;

    LOAD_STAGE(0, 0);
    asm volatile("cp.async.commit_group;");
    LOAD_STAGE(1, 1);
    asm volatile("cp.async.commit_group;");
    asm volatile("cp.async.wait_group 1;");
    __syncthreads();

    for (int kt = 0; kt < KTILES; ++kt) {
        if (kt + 2 < KTILES) {
            LOAD_STAGE(kt + 2, (kt + 2) % NSTAGE);
        }
        asm volatile("cp.async.commit_group;");

        const uint32_t sA = sbase + (uint32_t)(kt % NSTAGE) * stageBytes;
        const uint32_t sB = sA + bOffBytes;

        #pragma unroll
        for (int ks = 0; ks < 2; ++ks) {
            uint32_t ar[4][4];
            #pragma unroll
            for (int mi = 0; mi < 4; ++mi) {
                uint32_t addr = sA +
                    (uint32_t)((aRow + mi * 16) * LDS + ks * 16 + aKoff) * 2;
                asm volatile(
                    "ldmatrix.sync.aligned.m8n8.x4.shared.b16 {%0,%1,%2,%3}, [%4];"
                    : "=r"(ar[mi][0]), "=r"(ar[mi][1]),
                      "=r"(ar[mi][2]), "=r"(ar[mi][3])
                    : "r"(addr));
            }
            uint32_t br[4][2];
            #pragma unroll
            for (int p = 0; p < 2; ++p) {
                uint32_t addr = sB +
                    (uint32_t)((nW + p * 16 + bRowQ) * LDS + ks * 16 + bKoff) * 2;
                uint32_t r0, r1, r2, r3;
                asm volatile(
                    "ldmatrix.sync.aligned.m8n8.x4.shared.b16 {%0,%1,%2,%3}, [%4];"
                    : "=r"(r0), "=r"(r1), "=r"(r2), "=r"(r3)
                    : "r"(addr));
                br[2 * p][0]     = r0; br[2 * p][1]     = r1;
                br[2 * p + 1][0] = r2; br[2 * p + 1][1] = r3;
            }
            #pragma unroll
            for (int mi = 0; mi < 4; ++mi)
                #pragma unroll
                for (int ni = 0; ni < 4; ++ni)
                    asm volatile(
                        "mma.sync.aligned.m16n8k16.row.col.f32.f16.f16.f32 "
                        "{%0,%1,%2,%3}, {%4,%5,%6,%7}, {%8,%9}, {%0,%1,%2,%3};"
                        : "+f"(acc[mi][ni][0]), "+f"(acc[mi][ni][1]),
                          "+f"(acc[mi][ni][2]), "+f"(acc[mi][ni][3])
                        : "r"(ar[mi][0]), "r"(ar[mi][1]),
                          "r"(ar[mi][2]), "r"(ar[mi][3]),
                          "r"(br[ni][0]), "r"(br[ni][1]));
        }

        asm volatile("cp.async.wait_group 1;");
        __syncthreads();
    }

    #pragma unroll
    for (int mi = 0; mi < 4; ++mi) {
        #pragma unroll
        for (int ni = 0; ni < 4; ++ni) {
            int row = blockIdx.y * BM + mW + mi * 16 + (lane >> 2);
            int col = blockIdx.x * BN + nW + ni * 8 + ((lane & 3) << 1);
            float2 v0 = make_float2(acc[mi][ni][0], acc[mi][ni][1]);
            float2 v1 = make_float2(acc[mi][ni][2], acc[mi][ni][3]);
            *(float2*)&C[(size_t)row * SS + col]       = v0;
            *(float2*)&C[(size_t)(row + 8) * SS + col] = v1;
        }
    }
    #undef LOAD_STAGE
}

// ---------------------------------------------------------------------------
// Masked softmax over rows of 1024, in-place on C (= d_out).
// ---------------------------------------------------------------------------
__global__ void __launch_bounds__(256)
softmax_kernel(float* __restrict__ C, const int* __restrict__ mask,
               const float* __restrict__ bcp)
{
    const size_t row = blockIdx.x;
    float* p = C + row * 1024;
    const int* mp = mask + row * 1024;
    const int t = threadIdx.x;
    const float bias = bcp[0];

    float4 v = ((const float4*)p)[t];
    int4  mk = ((const int4*)mp)[t];

    float x0 = mk.x ? v.x + bias : NEGV;
    float x1 = mk.y ? v.y + bias : NEGV;
    float x2 = mk.z ? v.z + bias : NEGV;
    float x3 = mk.w ? v.w + bias : NEGV;

    float mx = fmaxf(fmaxf(x0, x1), fmaxf(x2, x3));
    #pragma unroll
    for (int o = 16; o; o >>= 1)
        mx = fmaxf(mx, __shfl_xor_sync(0xffffffffu, mx, o));

    __shared__ float red_m[8];
    __shared__ float red_s[8];
    if ((t & 31) == 0) red_m[t >> 5] = mx;
    __syncthreads();
    mx = red_m[0];
    #pragma unroll
    for (int i = 1; i < 8; ++i) mx = fmaxf(mx, red_m[i]);

    float e0 = expf(x0 - mx);
    float e1 = expf(x1 - mx);
    float e2 = expf(x2 - mx);
    float e3 = expf(x3 - mx);
    float s = e0 + e1 + e2 + e3;
    #pragma unroll
    for (int o = 16; o; o >>= 1)
        s += __shfl_xor_sync(0xffffffffu, s, o);
    if ((t & 31) == 0) red_s[t >> 5] = s;
    __syncthreads();
    float tot = red_s[0];
    #pragma unroll
    for (int i = 1; i < 8; ++i) tot += red_s[i];

    const float inv = 1.0f / tot;
    v.x = e0 * inv; v.y = e1 * inv; v.z = e2 * inv; v.w = e3 * inv;
    ((float4*)p)[t] = v;
}

// ---------------------------------------------------------------------------
// Launch
// ---------------------------------------------------------------------------
extern "C" void kernel_launch(void* const* d_in, const int* in_sizes, int n_in,
                              void* d_out, int out_size)
{
    const float* query = (const float*)d_in[0];
    const float* key   = (const float*)d_in[1];
    const int*   mask  = (const int*)  d_in[2];
    const float* Wq    = (const float*)d_in[3];
    const float* bq    = (const float*)d_in[4];
    const float* Wk    = (const float*)d_in[5];
    const float* bk    = (const float*)d_in[6];
    const float* Wc    = (const float*)d_in[7];
    const float* bc    = (const float*)d_in[8];
    float* out = (float*)d_out;

    __half *qc, *kc;
    cudaGetSymbolAddress((void**)&qc, g_Qc);
    cudaGetSymbolAddress((void**)&kc, g_Kc);

    const int smemBytes = 3 * (128 + 128) * 40 * 2;   // 61440
    cudaFuncSetAttribute(gemm_fp16_nt,
                         cudaFuncAttributeMaxDynamicSharedMemorySize, smemBytes);
    cudaFuncSetAttribute(proj_mma_kernel,
                         cudaFuncAttributeMaxDynamicSharedMemorySize, PROJ_SMEM);

    // Tensor-core projection (pure fp16): Q and K -> fp16 slabs (stride 1024)
    proj_mma_kernel<<<1024, 256, PROJ_SMEM>>>(query, key, Wq, bq, Wk, bk, Wc,
                                              qc, kc);

    // comb[b] = Qc[b] @ Kc[b]^T  (K=1024)
    gemm_fp16_nt<<<dim3(8, 8, 4), 256, smemBytes>>>(qc, kc, out);

    // mask + softmax, in-place
    softmax_kernel<<<BB * SS, 256>>>(out, mask, bc);
}